// round 1
// baseline (speedup 1.0000x reference)
#include <cuda_runtime.h>
#include <math.h>

#define BB 32
#define SS 512
#define DD 768
#define HH 12
#define EE 64

// Scratch (allocation-free rule: __device__ globals)
__device__ float g_q[BB*HH*SS*EE];     // [B,H,S,E]
__device__ float g_k[BB*HH*SS*EE];
__device__ float g_v[BB*HH*SS*EE];
__device__ float g_att[BB*SS*DD];      // [B,S,H*E] concat layout

// ---------------------------------------------------------------------------
// QKV projection: per (b,h,which): q[b,h] = x[b] @ W[h] + bias[h]
// GEMM [512 x 768] @ [768 x 64]; tile 128x64, BK=16, 256 thr, 8x4 per thread
// grid: (S/128, H, B*3)
// ---------------------------------------------------------------------------
__global__ __launch_bounds__(256) void qkv_kernel(
    const float* __restrict__ x,
    const float* __restrict__ Wq, const float* __restrict__ Wk, const float* __restrict__ Wv,
    const float* __restrict__ bq, const float* __restrict__ bk, const float* __restrict__ bv)
{
    const int mt    = blockIdx.x;       // 0..3
    const int h     = blockIdx.y;       // 0..11
    const int bz    = blockIdx.z;       // 0..95
    const int b     = bz / 3;
    const int which = bz % 3;

    const float* W    = (which == 0) ? Wq : (which == 1) ? Wk : Wv;
    const float* bias = (which == 0) ? bq : (which == 1) ? bk : bv;
    float*       out  = (which == 0) ? g_q : (which == 1) ? g_k : g_v;

    W    += h * DD * EE;
    bias += h * EE;

    const float* A = x + (size_t)b * SS * DD + (size_t)mt * 128 * DD;

    __shared__ float As[16][129];   // transposed A tile, padded (conflict-free)
    __shared__ float Bs[16][64];

    const int tid = threadIdx.x;
    const int ty  = tid >> 4;   // 0..15  -> rows ty*8..+7
    const int tx  = tid & 15;   // 0..15  -> cols tx*4..+3

    float acc[8][4];
    #pragma unroll
    for (int i = 0; i < 8; i++)
        #pragma unroll
        for (int j = 0; j < 4; j++) acc[i][j] = 0.f;

    for (int k0 = 0; k0 < DD; k0 += 16) {
        #pragma unroll
        for (int it = 0; it < 8; it++) {          // 128x16 A tile
            int idx = it * 256 + tid;
            int m  = idx >> 4;
            int kk = idx & 15;
            As[kk][m] = A[m * DD + k0 + kk];
        }
        #pragma unroll
        for (int it = 0; it < 4; it++) {          // 16x64 B tile
            int idx = it * 256 + tid;
            int kk = idx >> 6;
            int n  = idx & 63;
            Bs[kk][n] = W[(k0 + kk) * EE + n];
        }
        __syncthreads();

        #pragma unroll
        for (int kk = 0; kk < 16; kk++) {
            float a[8], bb[4];
            #pragma unroll
            for (int i = 0; i < 8; i++) a[i] = As[kk][ty * 8 + i];
            #pragma unroll
            for (int j = 0; j < 4; j++) bb[j] = Bs[kk][tx * 4 + j];
            #pragma unroll
            for (int i = 0; i < 8; i++)
                #pragma unroll
                for (int j = 0; j < 4; j++)
                    acc[i][j] += a[i] * bb[j];
        }
        __syncthreads();
    }

    float* outp = out + (((size_t)b * HH + h) * SS + (size_t)mt * 128) * EE;
    #pragma unroll
    for (int i = 0; i < 8; i++) {
        int m = ty * 8 + i;
        #pragma unroll
        for (int j = 0; j < 4; j++) {
            int n = tx * 4 + j;
            outp[m * EE + n] = acc[i][j] + bias[n];
        }
    }
}

// ---------------------------------------------------------------------------
// Flash attention: one block per (b, h, 64-row q tile). KV tiles of 32 rows.
// 256 threads as 16x16: thread owns s-rows ty*4..+3; s-cols tx*2..+1;
// acc E-cols tx*4..+3. Online softmax state replicated across tx group.
// grid: (S/64, H, B)
// ---------------------------------------------------------------------------
__global__ __launch_bounds__(256) void attn_kernel()
{
    const int qt = blockIdx.x;
    const int h  = blockIdx.y;
    const int b  = blockIdx.z;

    __shared__ float qs[64][65];
    __shared__ float ks[32][65];
    __shared__ float vs[32][65];
    __shared__ float ps[64][33];

    const int tid = threadIdx.x;
    const int ty  = tid >> 4;
    const int tx  = tid & 15;

    const float scale = 0.125f;  // 1/sqrt(64)

    const float* qptr  = g_q + (((size_t)b * HH + h) * SS + (size_t)qt * 64) * EE;
    const float* kbase = g_k + (((size_t)b * HH + h) * SS) * EE;
    const float* vbase = g_v + (((size_t)b * HH + h) * SS) * EE;

    #pragma unroll
    for (int it = 0; it < 16; it++) {   // load 64x64 q tile
        int idx = it * 256 + tid;
        int r = idx >> 6;
        int e = idx & 63;
        qs[r][e] = qptr[r * EE + e];
    }

    float m_i[4], l_i[4], acc[4][4];
    #pragma unroll
    for (int i = 0; i < 4; i++) {
        m_i[i] = -1e30f; l_i[i] = 0.f;
        #pragma unroll
        for (int j = 0; j < 4; j++) acc[i][j] = 0.f;
    }
    __syncthreads();

    for (int t0 = 0; t0 < SS; t0 += 32) {
        #pragma unroll
        for (int it = 0; it < 8; it++) {   // load 32x64 k,v tiles
            int idx = it * 256 + tid;
            int r = idx >> 6;
            int e = idx & 63;
            ks[r][e] = kbase[(t0 + r) * EE + e];
            vs[r][e] = vbase[(t0 + r) * EE + e];
        }
        __syncthreads();

        // s[4][2] = q-tile rows x kv-tile cols
        float s[4][2];
        #pragma unroll
        for (int i = 0; i < 4; i++) { s[i][0] = 0.f; s[i][1] = 0.f; }
        #pragma unroll 8
        for (int e = 0; e < 64; e++) {
            float a0 = qs[ty * 4 + 0][e];
            float a1 = qs[ty * 4 + 1][e];
            float a2 = qs[ty * 4 + 2][e];
            float a3 = qs[ty * 4 + 3][e];
            float b0 = ks[tx * 2 + 0][e];
            float b1 = ks[tx * 2 + 1][e];
            s[0][0] += a0 * b0; s[0][1] += a0 * b1;
            s[1][0] += a1 * b0; s[1][1] += a1 * b1;
            s[2][0] += a2 * b0; s[2][1] += a2 * b1;
            s[3][0] += a3 * b0; s[3][1] += a3 * b1;
        }
        #pragma unroll
        for (int i = 0; i < 4; i++) { s[i][0] *= scale; s[i][1] *= scale; }

        // row max across the 16 tx lanes (xor<16 stays in half-warp group)
        float rmax[4];
        #pragma unroll
        for (int i = 0; i < 4; i++) rmax[i] = fmaxf(s[i][0], s[i][1]);
        #pragma unroll
        for (int off = 1; off < 16; off <<= 1)
            #pragma unroll
            for (int i = 0; i < 4; i++)
                rmax[i] = fmaxf(rmax[i], __shfl_xor_sync(0xffffffffu, rmax[i], off));

        float p[4][2], rsum[4], corr[4];
        #pragma unroll
        for (int i = 0; i < 4; i++) {
            float mn = fmaxf(m_i[i], rmax[i]);
            corr[i]  = __expf(m_i[i] - mn);
            m_i[i]   = mn;
            p[i][0]  = __expf(s[i][0] - mn);
            p[i][1]  = __expf(s[i][1] - mn);
            rsum[i]  = p[i][0] + p[i][1];
        }
        #pragma unroll
        for (int off = 1; off < 16; off <<= 1)
            #pragma unroll
            for (int i = 0; i < 4; i++)
                rsum[i] += __shfl_xor_sync(0xffffffffu, rsum[i], off);
        #pragma unroll
        for (int i = 0; i < 4; i++) {
            l_i[i] = l_i[i] * corr[i] + rsum[i];
            #pragma unroll
            for (int j = 0; j < 4; j++) acc[i][j] *= corr[i];
            ps[ty * 4 + i][tx * 2 + 0] = p[i][0];
            ps[ty * 4 + i][tx * 2 + 1] = p[i][1];
        }
        __syncthreads();

        // acc += P @ V  (thread owns E-cols tx*4..+3)
        #pragma unroll 8
        for (int kv = 0; kv < 32; kv++) {
            float pv0 = ps[ty * 4 + 0][kv];
            float pv1 = ps[ty * 4 + 1][kv];
            float pv2 = ps[ty * 4 + 2][kv];
            float pv3 = ps[ty * 4 + 3][kv];
            float v0 = vs[kv][tx * 4 + 0];
            float v1 = vs[kv][tx * 4 + 1];
            float v2 = vs[kv][tx * 4 + 2];
            float v3 = vs[kv][tx * 4 + 3];
            acc[0][0] += pv0 * v0; acc[0][1] += pv0 * v1; acc[0][2] += pv0 * v2; acc[0][3] += pv0 * v3;
            acc[1][0] += pv1 * v0; acc[1][1] += pv1 * v1; acc[1][2] += pv1 * v2; acc[1][3] += pv1 * v3;
            acc[2][0] += pv2 * v0; acc[2][1] += pv2 * v1; acc[2][2] += pv2 * v2; acc[2][3] += pv2 * v3;
            acc[3][0] += pv3 * v0; acc[3][1] += pv3 * v1; acc[3][2] += pv3 * v2; acc[3][3] += pv3 * v3;
        }
        __syncthreads();
    }

    // normalize + write into [B,S,H*E] concat layout
    float* outp = g_att + ((size_t)b * SS + (size_t)qt * 64) * DD + h * EE;
    #pragma unroll
    for (int i = 0; i < 4; i++) {
        float inv = 1.f / l_i[i];
        int r = ty * 4 + i;
        #pragma unroll
        for (int j = 0; j < 4; j++)
            outp[r * DD + tx * 4 + j] = acc[i][j] * inv;
    }
}

// ---------------------------------------------------------------------------
// Output projection: [B*S x 768] @ Wo[768 x 768] + bo
// grid: (B*S/128, D/64)
// ---------------------------------------------------------------------------
__global__ __launch_bounds__(256) void proj_kernel(
    const float* __restrict__ Wo, const float* __restrict__ bo,
    float* __restrict__ out)
{
    const int mt = blockIdx.x;      // 0..127
    const int nt = blockIdx.y;      // 0..11

    __shared__ float As[16][129];
    __shared__ float Bs[16][64];

    const float* A  = g_att + (size_t)mt * 128 * DD;
    const float* Bm = Wo + nt * 64;

    const int tid = threadIdx.x;
    const int ty  = tid >> 4;
    const int tx  = tid & 15;

    float acc[8][4];
    #pragma unroll
    for (int i = 0; i < 8; i++)
        #pragma unroll
        for (int j = 0; j < 4; j++) acc[i][j] = 0.f;

    for (int k0 = 0; k0 < DD; k0 += 16) {
        #pragma unroll
        for (int it = 0; it < 8; it++) {
            int idx = it * 256 + tid;
            int m  = idx >> 4;
            int kk = idx & 15;
            As[kk][m] = A[m * DD + k0 + kk];
        }
        #pragma unroll
        for (int it = 0; it < 4; it++) {
            int idx = it * 256 + tid;
            int kk = idx >> 6;
            int n  = idx & 63;
            Bs[kk][n] = Bm[(k0 + kk) * DD + n];
        }
        __syncthreads();

        #pragma unroll
        for (int kk = 0; kk < 16; kk++) {
            float a[8], bb[4];
            #pragma unroll
            for (int i = 0; i < 8; i++) a[i] = As[kk][ty * 8 + i];
            #pragma unroll
            for (int j = 0; j < 4; j++) bb[j] = Bs[kk][tx * 4 + j];
            #pragma unroll
            for (int i = 0; i < 8; i++)
                #pragma unroll
                for (int j = 0; j < 4; j++)
                    acc[i][j] += a[i] * bb[j];
        }
        __syncthreads();
    }

    float* outp = out + (size_t)mt * 128 * DD + nt * 64;
    #pragma unroll
    for (int i = 0; i < 8; i++) {
        int m = ty * 8 + i;
        #pragma unroll
        for (int j = 0; j < 4; j++) {
            int n = tx * 4 + j;
            outp[m * DD + n] = acc[i][j] + bo[nt * 64 + n];
        }
    }
}

extern "C" void kernel_launch(void* const* d_in, const int* in_sizes, int n_in,
                              void* d_out, int out_size)
{
    const float* x  = (const float*)d_in[0];
    const float* Wq = (const float*)d_in[1];
    const float* Wk = (const float*)d_in[2];
    const float* Wv = (const float*)d_in[3];
    const float* bq = (const float*)d_in[4];
    const float* bk = (const float*)d_in[5];
    const float* bv = (const float*)d_in[6];
    const float* Wo = (const float*)d_in[7];
    const float* bo = (const float*)d_in[8];
    float* out = (float*)d_out;

    qkv_kernel<<<dim3(SS / 128, HH, BB * 3), 256>>>(x, Wq, Wk, Wv, bq, bk, bv);
    attn_kernel<<<dim3(SS / 64, HH, BB), 256>>>();
    proj_kernel<<<dim3(BB * SS / 128, DD / 64), 256>>>(Wo, bo, out);
}

// round 3
// speedup vs baseline: 1.7774x; 1.7774x over previous
#include <cuda_runtime.h>
#include <cuda_bf16.h>
#include <math.h>
#include <stdint.h>

#define BB 32
#define SS 512
#define DD 768
#define HH 12
#define EE 64

#define M_TOT (BB*SS)        // 16384
#define N_QKV (3*DD)         // 2304
#define K2    (3*DD)         // split-K: A'=[hi|hi|lo], B'=[hi|lo|hi]

#define TBM 128
#define TBN 128
#define TBK 64               // bf16 elems per k-chunk (128B rows -> SW128)
#define NSTAGE 3
#define STAGE_BYTES (2*TBM*TBK*2)            // A tile + B tile = 32KB
#define SMEM_TOTAL (NSTAGE*STAGE_BYTES)      // 96KB
#define NKT (K2/TBK)         // 36

// ---------------- device scratch (allocation-free rule) ----------------
__device__ __nv_bfloat16 g_xs[M_TOT*K2];      // x split  [m][k']
__device__ __nv_bfloat16 g_as[M_TOT*K2];      // attn-out split [m][k']
__device__ __nv_bfloat16 g_wqkvs[N_QKV*K2];   // qkv weights split [n][k']
__device__ __nv_bfloat16 g_wos[DD*K2];        // Wo^T split [n][k']
__device__ float g_q[BB*HH*SS*EE];            // [B,H,S,E]
__device__ float g_k[BB*HH*SS*EE];
__device__ float g_v[BB*HH*SS*EE];

// ---------------- helpers ----------------
#define SW128(o) ((o) ^ (((o) >> 3) & 0x70))

__device__ __forceinline__ uint32_t smem_u32(const void* p) {
    return (uint32_t)__cvta_generic_to_shared(p);
}
__device__ __forceinline__ void cp16(uint32_t dst, const void* src) {
    asm volatile("cp.async.cg.shared.global [%0], [%1], 16;" :: "r"(dst), "l"(src) : "memory");
}
__device__ __forceinline__ void cp_commit() {
    asm volatile("cp.async.commit_group;" ::: "memory");
}
template <int N> __device__ __forceinline__ void cp_wait() {
    asm volatile("cp.async.wait_group %0;" :: "n"(N) : "memory");
}
__device__ __forceinline__ void ldsm4(uint32_t& a, uint32_t& b, uint32_t& c, uint32_t& d,
                                      uint32_t addr) {
    asm volatile("ldmatrix.sync.aligned.m8n8.x4.shared.b16 {%0,%1,%2,%3}, [%4];"
                 : "=r"(a), "=r"(b), "=r"(c), "=r"(d) : "r"(addr));
}
__device__ __forceinline__ void mma16816(float& c0, float& c1, float& c2, float& c3,
                                         uint32_t a0, uint32_t a1, uint32_t a2, uint32_t a3,
                                         uint32_t b0, uint32_t b1) {
    asm volatile(
        "mma.sync.aligned.m16n8k16.row.col.f32.bf16.bf16.f32 "
        "{%0,%1,%2,%3}, {%4,%5,%6,%7}, {%8,%9}, {%0,%1,%2,%3};"
        : "+f"(c0), "+f"(c1), "+f"(c2), "+f"(c3)
        : "r"(a0), "r"(a1), "r"(a2), "r"(a3), "r"(b0), "r"(b1));
}

// ---------------------------------------------------------------------------
// prep kernels
// ---------------------------------------------------------------------------
__global__ void prep_x(const float* __restrict__ x) {
    int i = blockIdx.x * 256 + threadIdx.x;
    if (i >= M_TOT * DD) return;
    int m = i / DD, k = i - (i / DD) * DD;
    float v = x[i];
    __nv_bfloat16 h = __float2bfloat16(v);
    __nv_bfloat16 l = __float2bfloat16(v - __bfloat162float(h));
    size_t base = (size_t)m * K2 + k;
    g_xs[base]          = h;
    g_xs[base + DD]     = h;
    g_xs[base + 2 * DD] = l;
}
__global__ void prep_wqkv(const float* __restrict__ Wq, const float* __restrict__ Wk,
                          const float* __restrict__ Wv) {
    int i = blockIdx.x * 256 + threadIdx.x;
    if (i >= N_QKV * DD) return;
    int n = i / DD, k = i - (i / DD) * DD;
    int which = n / DD;
    int rem = n - which * DD;
    int h = rem >> 6, e = rem & 63;
    const float* W = (which == 0) ? Wq : (which == 1) ? Wk : Wv;
    float v = W[((size_t)h * DD + k) * EE + e];
    __nv_bfloat16 hv = __float2bfloat16(v);
    __nv_bfloat16 lv = __float2bfloat16(v - __bfloat162float(hv));
    size_t base = (size_t)n * K2 + k;
    g_wqkvs[base]          = hv;
    g_wqkvs[base + DD]     = lv;
    g_wqkvs[base + 2 * DD] = hv;
}
__global__ void prep_wo(const float* __restrict__ Wo) {
    int i = blockIdx.x * 256 + threadIdx.x;
    if (i >= DD * DD) return;
    int n = i / DD, k = i - (i / DD) * DD;
    float v = Wo[(size_t)k * DD + n];
    __nv_bfloat16 hv = __float2bfloat16(v);
    __nv_bfloat16 lv = __float2bfloat16(v - __bfloat162float(hv));
    size_t base = (size_t)n * K2 + k;
    g_wos[base]          = hv;
    g_wos[base + DD]     = lv;
    g_wos[base + 2 * DD] = hv;
}

// ---------------------------------------------------------------------------
// bf16 mma.sync GEMM, 128x128 block, 3-stage cp.async, 8 warps (2x4)
// ---------------------------------------------------------------------------
__global__ __launch_bounds__(256) void gemm_kernel(
    int mode, const float* __restrict__ b0, const float* __restrict__ b1,
    const float* __restrict__ b2, float* __restrict__ out)
{
    extern __shared__ char smem[];
    const uint32_t sbase = smem_u32(smem);
    const int tid  = threadIdx.x;
    const int lane = tid & 31;
    const int warp = tid >> 5;
    const int wm = warp >> 2;        // 0..1
    const int wn = warp & 3;         // 0..3

    const int bn = blockIdx.x, bm = blockIdx.y;

    const __nv_bfloat16* A  = mode ? g_as : g_xs;
    const __nv_bfloat16* Bw = mode ? g_wos : g_wqkvs;
    const char* Abase = (const char*)(A  + (size_t)bm * TBM * K2);
    const char* Bbase = (const char*)(Bw + (size_t)bn * TBN * K2);

    auto load_stage = [&](int kt, int s) {
        uint32_t sb = sbase + s * STAGE_BYTES;
        size_t kb = (size_t)kt * (TBK * 2);
        #pragma unroll
        for (int i = 0; i < 4; i++) {
            int idx = i * 256 + tid;
            int r = idx >> 3, c = idx & 7;
            cp16(sb + SW128(r * 128 + c * 16),
                 Abase + (size_t)r * (K2 * 2) + kb + c * 16);
        }
        #pragma unroll
        for (int i = 0; i < 4; i++) {
            int idx = i * 256 + tid;
            int r = idx >> 3, c = idx & 7;
            cp16(sb + 16384 + SW128(r * 128 + c * 16),
                 Bbase + (size_t)r * (K2 * 2) + kb + c * 16);
        }
        cp_commit();
    };

    float acc[4][4][4];
    #pragma unroll
    for (int mi = 0; mi < 4; mi++)
        #pragma unroll
        for (int ni = 0; ni < 4; ni++)
            #pragma unroll
            for (int j = 0; j < 4; j++) acc[mi][ni][j] = 0.f;

    load_stage(0, 0);
    load_stage(1, 1);

    const int a_row = wm * 64 + (lane & 15);
    const int a_ch  = lane >> 4;
    const int b_row = wn * 32 + (lane & 7) + ((lane >> 3) & 1) * 8;
    const int b_ch  = lane >> 4;

    for (int kt = 0; kt < NKT; kt++) {
        cp_wait<NSTAGE - 2>();
        __syncthreads();

        if (kt + NSTAGE - 1 < NKT)
            load_stage(kt + NSTAGE - 1, (kt + NSTAGE - 1) % NSTAGE);
        else
            cp_commit();

        uint32_t sb = sbase + (kt % NSTAGE) * STAGE_BYTES;

        #pragma unroll
        for (int ks = 0; ks < 4; ks++) {
            uint32_t af[4][4];
            #pragma unroll
            for (int mi = 0; mi < 4; mi++) {
                int row = a_row + mi * 16;
                int ch  = ks * 2 + a_ch;
                ldsm4(af[mi][0], af[mi][1], af[mi][2], af[mi][3],
                      sb + SW128(row * 128 + ch * 16));
            }
            uint32_t bfr[4][2];
            #pragma unroll
            for (int p = 0; p < 2; p++) {
                int row = b_row + p * 16;
                int ch  = ks * 2 + b_ch;
                uint32_t r0, r1, r2, r3;
                ldsm4(r0, r1, r2, r3, sb + 16384 + SW128(row * 128 + ch * 16));
                bfr[p * 2 + 0][0] = r0; bfr[p * 2 + 0][1] = r2;
                bfr[p * 2 + 1][0] = r1; bfr[p * 2 + 1][1] = r3;
            }
            #pragma unroll
            for (int mi = 0; mi < 4; mi++)
                #pragma unroll
                for (int ni = 0; ni < 4; ni++)
                    mma16816(acc[mi][ni][0], acc[mi][ni][1], acc[mi][ni][2], acc[mi][ni][3],
                             af[mi][0], af[mi][1], af[mi][2], af[mi][3],
                             bfr[ni][0], bfr[ni][1]);
        }
        __syncthreads();
    }

    const int gid = lane >> 2;
    const int tg  = lane & 3;
    #pragma unroll
    for (int mi = 0; mi < 4; mi++) {
        #pragma unroll
        for (int half = 0; half < 2; half++) {
            int m = bm * TBM + wm * 64 + mi * 16 + gid + half * 8;
            #pragma unroll
            for (int ni = 0; ni < 4; ni++) {
                int n = bn * TBN + wn * 32 + ni * 8 + tg * 2;
                float v0 = acc[mi][ni][half * 2 + 0];
                float v1 = acc[mi][ni][half * 2 + 1];
                if (mode == 0) {
                    int which = n / DD;
                    int rem = n - which * DD;
                    int h = rem >> 6, e = rem & 63;
                    const float* bp = ((which == 0) ? b0 : (which == 1) ? b1 : b2) + h * EE + e;
                    float* ob = (which == 0) ? g_q : (which == 1) ? g_k : g_v;
                    float* op = ob + ((((size_t)(m >> 9) * HH + h) * SS + (m & 511)) * EE) + e;
                    float2 w; w.x = v0 + bp[0]; w.y = v1 + bp[1];
                    *(float2*)op = w;
                } else {
                    float2 w; w.x = v0 + b0[n]; w.y = v1 + b0[n + 1];
                    *(float2*)(out + (size_t)m * DD + n) = w;
                }
            }
        }
    }
}

// ---------------------------------------------------------------------------
// Flash attention (fp32 SIMT); writes split bf16 rows into g_as
// ---------------------------------------------------------------------------
__global__ __launch_bounds__(256) void attn_kernel()
{
    const int qt = blockIdx.x;
    const int h  = blockIdx.y;
    const int b  = blockIdx.z;

    __shared__ float qs[64][65];
    __shared__ float ks[32][65];
    __shared__ float vs[32][65];
    __shared__ float ps[64][33];

    const int tid = threadIdx.x;
    const int ty  = tid >> 4;
    const int tx  = tid & 15;

    const float scale = 0.125f;

    const float* qptr  = g_q + (((size_t)b * HH + h) * SS + (size_t)qt * 64) * EE;
    const float* kbase = g_k + (((size_t)b * HH + h) * SS) * EE;
    const float* vbase = g_v + (((size_t)b * HH + h) * SS) * EE;

    #pragma unroll
    for (int it = 0; it < 16; it++) {
        int idx = it * 256 + tid;
        int r = idx >> 6, e = idx & 63;
        qs[r][e] = qptr[r * EE + e];
    }

    float m_i[4], l_i[4], acc[4][4];
    #pragma unroll
    for (int i = 0; i < 4; i++) {
        m_i[i] = -1e30f; l_i[i] = 0.f;
        #pragma unroll
        for (int j = 0; j < 4; j++) acc[i][j] = 0.f;
    }
    __syncthreads();

    for (int t0 = 0; t0 < SS; t0 += 32) {
        #pragma unroll
        for (int it = 0; it < 8; it++) {
            int idx = it * 256 + tid;
            int r = idx >> 6, e = idx & 63;
            ks[r][e] = kbase[(t0 + r) * EE + e];
            vs[r][e] = vbase[(t0 + r) * EE + e];
        }
        __syncthreads();

        float s[4][2];
        #pragma unroll
        for (int i = 0; i < 4; i++) { s[i][0] = 0.f; s[i][1] = 0.f; }
        #pragma unroll 8
        for (int e = 0; e < 64; e++) {
            float a0 = qs[ty * 4 + 0][e];
            float a1 = qs[ty * 4 + 1][e];
            float a2 = qs[ty * 4 + 2][e];
            float a3 = qs[ty * 4 + 3][e];
            float b0 = ks[tx * 2 + 0][e];
            float b1 = ks[tx * 2 + 1][e];
            s[0][0] += a0 * b0; s[0][1] += a0 * b1;
            s[1][0] += a1 * b0; s[1][1] += a1 * b1;
            s[2][0] += a2 * b0; s[2][1] += a2 * b1;
            s[3][0] += a3 * b0; s[3][1] += a3 * b1;
        }
        #pragma unroll
        for (int i = 0; i < 4; i++) { s[i][0] *= scale; s[i][1] *= scale; }

        float rmax[4];
        #pragma unroll
        for (int i = 0; i < 4; i++) rmax[i] = fmaxf(s[i][0], s[i][1]);
        #pragma unroll
        for (int off = 1; off < 16; off <<= 1)
            #pragma unroll
            for (int i = 0; i < 4; i++)
                rmax[i] = fmaxf(rmax[i], __shfl_xor_sync(0xffffffffu, rmax[i], off));

        float p[4][2], rsum[4], corr[4];
        #pragma unroll
        for (int i = 0; i < 4; i++) {
            float mn = fmaxf(m_i[i], rmax[i]);
            corr[i]  = __expf(m_i[i] - mn);
            m_i[i]   = mn;
            p[i][0]  = __expf(s[i][0] - mn);
            p[i][1]  = __expf(s[i][1] - mn);
            rsum[i]  = p[i][0] + p[i][1];
        }
        #pragma unroll
        for (int off = 1; off < 16; off <<= 1)
            #pragma unroll
            for (int i = 0; i < 4; i++)
                rsum[i] += __shfl_xor_sync(0xffffffffu, rsum[i], off);
        #pragma unroll
        for (int i = 0; i < 4; i++) {
            l_i[i] = l_i[i] * corr[i] + rsum[i];
            #pragma unroll
            for (int j = 0; j < 4; j++) acc[i][j] *= corr[i];
            ps[ty * 4 + i][tx * 2 + 0] = p[i][0];
            ps[ty * 4 + i][tx * 2 + 1] = p[i][1];
        }
        __syncthreads();

        #pragma unroll 8
        for (int kv = 0; kv < 32; kv++) {
            float pv0 = ps[ty * 4 + 0][kv];
            float pv1 = ps[ty * 4 + 1][kv];
            float pv2 = ps[ty * 4 + 2][kv];
            float pv3 = ps[ty * 4 + 3][kv];
            float v0 = vs[kv][tx * 4 + 0];
            float v1 = vs[kv][tx * 4 + 1];
            float v2 = vs[kv][tx * 4 + 2];
            float v3 = vs[kv][tx * 4 + 3];
            acc[0][0] += pv0 * v0; acc[0][1] += pv0 * v1; acc[0][2] += pv0 * v2; acc[0][3] += pv0 * v3;
            acc[1][0] += pv1 * v0; acc[1][1] += pv1 * v1; acc[1][2] += pv1 * v2; acc[1][3] += pv1 * v3;
            acc[2][0] += pv2 * v0; acc[2][1] += pv2 * v1; acc[2][2] += pv2 * v2; acc[2][3] += pv2 * v3;
            acc[3][0] += pv3 * v0; acc[3][1] += pv3 * v1; acc[3][2] += pv3 * v2; acc[3][3] += pv3 * v3;
        }
        __syncthreads();
    }

    size_t mrow = (size_t)b * SS + (size_t)qt * 64;
    #pragma unroll
    for (int i = 0; i < 4; i++) {
        float inv = 1.f / l_i[i];
        int r = ty * 4 + i;
        size_t base = (mrow + r) * K2 + h * EE + tx * 4;
        #pragma unroll
        for (int j = 0; j < 4; j++) {
            float val = acc[i][j] * inv;
            __nv_bfloat16 hv = __float2bfloat16(val);
            __nv_bfloat16 lv = __float2bfloat16(val - __bfloat162float(hv));
            g_as[base + j]          = hv;
            g_as[base + j + DD]     = hv;
            g_as[base + j + 2 * DD] = lv;
        }
    }
}

// ---------------------------------------------------------------------------
extern "C" void kernel_launch(void* const* d_in, const int* in_sizes, int n_in,
                              void* d_out, int out_size)
{
    const float* x  = (const float*)d_in[0];
    const float* Wq = (const float*)d_in[1];
    const float* Wk = (const float*)d_in[2];
    const float* Wv = (const float*)d_in[3];
    const float* bq = (const float*)d_in[4];
    const float* bk = (const float*)d_in[5];
    const float* bv = (const float*)d_in[6];
    const float* Wo = (const float*)d_in[7];
    const float* bo = (const float*)d_in[8];
    float* out = (float*)d_out;

    cudaFuncSetAttribute(gemm_kernel, cudaFuncAttributeMaxDynamicSharedMemorySize, SMEM_TOTAL);

    prep_x<<<(M_TOT * DD + 255) / 256, 256>>>(x);
    prep_wqkv<<<(N_QKV * DD + 255) / 256, 256>>>(Wq, Wk, Wv);
    prep_wo<<<(DD * DD + 255) / 256, 256>>>(Wo);

    gemm_kernel<<<dim3(N_QKV / TBN, M_TOT / TBM), 256, SMEM_TOTAL>>>(
        0, bq, bk, bv, nullptr);

    attn_kernel<<<dim3(SS / 64, HH, BB), 256>>>();

    gemm_kernel<<<dim3(DD / TBN, M_TOT / TBM), 256, SMEM_TOTAL>>>(
        1, bo, bo, bo, out);
}

// round 5
// speedup vs baseline: 2.8255x; 1.5897x over previous
#include <cuda_runtime.h>
#include <cuda_bf16.h>
#include <math.h>
#include <stdint.h>

#define BB 32
#define SS 512
#define DD 768
#define HH 12
#define EE 64

#define M_TOT (BB*SS)        // 16384
#define N_QKV (3*DD)         // 2304
#define K2    (3*DD)         // split-K: A'=[hi|hi|lo], B'=[hi|lo|hi]

#define TBM 128
#define TBN 128
#define TBK 64
#define NSTAGE 3
#define STAGE_BYTES (2*TBM*TBK*2)            // 32KB
#define SMEM_TOTAL (NSTAGE*STAGE_BYTES)      // 96KB
#define NKT (K2/TBK)         // 36

// ---------------- device scratch ----------------
__device__ __nv_bfloat16 g_xs[M_TOT*K2];      // x split  [m][k']
__device__ __nv_bfloat16 g_as[M_TOT*K2];      // attn-out split [m][k']
__device__ __nv_bfloat16 g_wqkvs[N_QKV*K2];   // qkv weights split [n][k']
__device__ __nv_bfloat16 g_wos[DD*K2];        // Wo^T split [n][k']
__device__ __nv_bfloat16 g_qhi[BB*HH*SS*EE];  // [B,H,S,E]
__device__ __nv_bfloat16 g_qlo[BB*HH*SS*EE];
__device__ __nv_bfloat16 g_khi[BB*HH*SS*EE];
__device__ __nv_bfloat16 g_klo[BB*HH*SS*EE];
__device__ __nv_bfloat16 g_vhi[BB*HH*SS*EE];
__device__ __nv_bfloat16 g_vlo[BB*HH*SS*EE];

// ---------------- helpers ----------------
#define SW128(o) ((o) ^ (((o) >> 3) & 0x70))

__device__ __forceinline__ uint32_t smem_u32(const void* p) {
    return (uint32_t)__cvta_generic_to_shared(p);
}
__device__ __forceinline__ void cp16(uint32_t dst, const void* src) {
    asm volatile("cp.async.cg.shared.global [%0], [%1], 16;" :: "r"(dst), "l"(src) : "memory");
}
__device__ __forceinline__ void cp_commit() {
    asm volatile("cp.async.commit_group;" ::: "memory");
}
template <int N> __device__ __forceinline__ void cp_wait() {
    asm volatile("cp.async.wait_group %0;" :: "n"(N) : "memory");
}
__device__ __forceinline__ void ldsm4(uint32_t& a, uint32_t& b, uint32_t& c, uint32_t& d,
                                      uint32_t addr) {
    asm volatile("ldmatrix.sync.aligned.m8n8.x4.shared.b16 {%0,%1,%2,%3}, [%4];"
                 : "=r"(a), "=r"(b), "=r"(c), "=r"(d) : "r"(addr));
}
__device__ __forceinline__ void ldsm4t(uint32_t& a, uint32_t& b, uint32_t& c, uint32_t& d,
                                       uint32_t addr) {
    asm volatile("ldmatrix.sync.aligned.m8n8.x4.trans.shared.b16 {%0,%1,%2,%3}, [%4];"
                 : "=r"(a), "=r"(b), "=r"(c), "=r"(d) : "r"(addr));
}
__device__ __forceinline__ void mma16816(float& c0, float& c1, float& c2, float& c3,
                                         uint32_t a0, uint32_t a1, uint32_t a2, uint32_t a3,
                                         uint32_t b0, uint32_t b1) {
    asm volatile(
        "mma.sync.aligned.m16n8k16.row.col.f32.bf16.bf16.f32 "
        "{%0,%1,%2,%3}, {%4,%5,%6,%7}, {%8,%9}, {%0,%1,%2,%3};"
        : "+f"(c0), "+f"(c1), "+f"(c2), "+f"(c3)
        : "r"(a0), "r"(a1), "r"(a2), "r"(a3), "r"(b0), "r"(b1));
}
// pack hi parts (truncate to bf16) of two fp32: {lo16=hi(v0), hi16=hi(v1)}
__device__ __forceinline__ uint32_t pack_hi(float v0, float v1) {
    return __byte_perm(__float_as_uint(v0), __float_as_uint(v1), 0x7632);
}
__device__ __forceinline__ float trunc_bf(float v) {
    return __uint_as_float(__float_as_uint(v) & 0xffff0000u);
}
// pack two fp32 rounded to bf16: {lo16=bf(l0), hi16=bf(l1)}
__device__ __forceinline__ uint32_t pack_rn(float l0, float l1) {
    uint32_t r;
    asm("cvt.rn.bf16x2.f32 %0, %1, %2;" : "=r"(r) : "f"(l1), "f"(l0));
    return r;
}

// ---------------------------------------------------------------------------
// prep kernels
// ---------------------------------------------------------------------------
__global__ void prep_x(const float* __restrict__ x) {
    int i = blockIdx.x * 256 + threadIdx.x;
    if (i >= M_TOT * DD) return;
    int m = i / DD, k = i - (i / DD) * DD;
    float v = x[i];
    __nv_bfloat16 h = __float2bfloat16(v);
    __nv_bfloat16 l = __float2bfloat16(v - __bfloat162float(h));
    size_t base = (size_t)m * K2 + k;
    g_xs[base]          = h;
    g_xs[base + DD]     = h;
    g_xs[base + 2 * DD] = l;
}
__global__ void prep_wqkv(const float* __restrict__ Wq, const float* __restrict__ Wk,
                          const float* __restrict__ Wv) {
    int i = blockIdx.x * 256 + threadIdx.x;
    if (i >= N_QKV * DD) return;
    int n = i / DD, k = i - (i / DD) * DD;
    int which = n / DD;
    int rem = n - which * DD;
    int h = rem >> 6, e = rem & 63;
    const float* W = (which == 0) ? Wq : (which == 1) ? Wk : Wv;
    float v = W[((size_t)h * DD + k) * EE + e];
    __nv_bfloat16 hv = __float2bfloat16(v);
    __nv_bfloat16 lv = __float2bfloat16(v - __bfloat162float(hv));
    size_t base = (size_t)n * K2 + k;
    g_wqkvs[base]          = hv;
    g_wqkvs[base + DD]     = lv;
    g_wqkvs[base + 2 * DD] = hv;
}
__global__ void prep_wo(const float* __restrict__ Wo) {
    int i = blockIdx.x * 256 + threadIdx.x;
    if (i >= DD * DD) return;
    int n = i / DD, k = i - (i / DD) * DD;
    float v = Wo[(size_t)k * DD + n];
    __nv_bfloat16 hv = __float2bfloat16(v);
    __nv_bfloat16 lv = __float2bfloat16(v - __bfloat162float(hv));
    size_t base = (size_t)n * K2 + k;
    g_wos[base]          = hv;
    g_wos[base + DD]     = lv;
    g_wos[base + 2 * DD] = hv;
}

// ---------------------------------------------------------------------------
// bf16 mma.sync GEMM, 128x128 block, 3-stage cp.async, 8 warps (2x4)
// mode 0 epilogue: write split q/k/v bf16 [B,H,S,E]
// mode 1 epilogue: write fp32 out
// ---------------------------------------------------------------------------
__global__ __launch_bounds__(256) void gemm_kernel(
    int mode, const float* __restrict__ b0, const float* __restrict__ b1,
    const float* __restrict__ b2, float* __restrict__ out)
{
    extern __shared__ char smem[];
    const uint32_t sbase = smem_u32(smem);
    const int tid  = threadIdx.x;
    const int lane = tid & 31;
    const int warp = tid >> 5;
    const int wm = warp >> 2;
    const int wn = warp & 3;

    const int bn = blockIdx.x, bm = blockIdx.y;

    const __nv_bfloat16* A  = mode ? g_as : g_xs;
    const __nv_bfloat16* Bw = mode ? g_wos : g_wqkvs;
    const char* Abase = (const char*)(A  + (size_t)bm * TBM * K2);
    const char* Bbase = (const char*)(Bw + (size_t)bn * TBN * K2);

    auto load_stage = [&](int kt, int s) {
        uint32_t sb = sbase + s * STAGE_BYTES;
        size_t kb = (size_t)kt * (TBK * 2);
        #pragma unroll
        for (int i = 0; i < 4; i++) {
            int idx = i * 256 + tid;
            int r = idx >> 3, c = idx & 7;
            cp16(sb + SW128(r * 128 + c * 16),
                 Abase + (size_t)r * (K2 * 2) + kb + c * 16);
        }
        #pragma unroll
        for (int i = 0; i < 4; i++) {
            int idx = i * 256 + tid;
            int r = idx >> 3, c = idx & 7;
            cp16(sb + 16384 + SW128(r * 128 + c * 16),
                 Bbase + (size_t)r * (K2 * 2) + kb + c * 16);
        }
        cp_commit();
    };

    float acc[4][4][4];
    #pragma unroll
    for (int mi = 0; mi < 4; mi++)
        #pragma unroll
        for (int ni = 0; ni < 4; ni++)
            #pragma unroll
            for (int j = 0; j < 4; j++) acc[mi][ni][j] = 0.f;

    load_stage(0, 0);
    load_stage(1, 1);

    const int a_row = wm * 64 + (lane & 15);
    const int a_ch  = lane >> 4;
    const int b_row = wn * 32 + (lane & 7) + ((lane >> 3) & 1) * 8;
    const int b_ch  = lane >> 4;

    for (int kt = 0; kt < NKT; kt++) {
        cp_wait<NSTAGE - 2>();
        __syncthreads();

        if (kt + NSTAGE - 1 < NKT)
            load_stage(kt + NSTAGE - 1, (kt + NSTAGE - 1) % NSTAGE);
        else
            cp_commit();

        uint32_t sb = sbase + (kt % NSTAGE) * STAGE_BYTES;

        #pragma unroll
        for (int ks = 0; ks < 4; ks++) {
            uint32_t af[4][4];
            #pragma unroll
            for (int mi = 0; mi < 4; mi++) {
                int row = a_row + mi * 16;
                int ch  = ks * 2 + a_ch;
                ldsm4(af[mi][0], af[mi][1], af[mi][2], af[mi][3],
                      sb + SW128(row * 128 + ch * 16));
            }
            uint32_t bfr[4][2];
            #pragma unroll
            for (int p = 0; p < 2; p++) {
                int row = b_row + p * 16;
                int ch  = ks * 2 + b_ch;
                uint32_t r0, r1, r2, r3;
                ldsm4(r0, r1, r2, r3, sb + 16384 + SW128(row * 128 + ch * 16));
                bfr[p * 2 + 0][0] = r0; bfr[p * 2 + 0][1] = r2;
                bfr[p * 2 + 1][0] = r1; bfr[p * 2 + 1][1] = r3;
            }
            #pragma unroll
            for (int mi = 0; mi < 4; mi++)
                #pragma unroll
                for (int ni = 0; ni < 4; ni++)
                    mma16816(acc[mi][ni][0], acc[mi][ni][1], acc[mi][ni][2], acc[mi][ni][3],
                             af[mi][0], af[mi][1], af[mi][2], af[mi][3],
                             bfr[ni][0], bfr[ni][1]);
        }
        __syncthreads();
    }

    const int gid = lane >> 2;
    const int tg  = lane & 3;
    #pragma unroll
    for (int mi = 0; mi < 4; mi++) {
        #pragma unroll
        for (int half = 0; half < 2; half++) {
            int m = bm * TBM + wm * 64 + mi * 16 + gid + half * 8;
            #pragma unroll
            for (int ni = 0; ni < 4; ni++) {
                int n = bn * TBN + wn * 32 + ni * 8 + tg * 2;
                float v0 = acc[mi][ni][half * 2 + 0];
                float v1 = acc[mi][ni][half * 2 + 1];
                if (mode == 0) {
                    int which = n / DD;
                    int rem = n - which * DD;
                    int h = rem >> 6, e = rem & 63;
                    const float* bp = ((which == 0) ? b0 : (which == 1) ? b1 : b2) + h * EE + e;
                    v0 += bp[0]; v1 += bp[1];
                    uint32_t hi = pack_hi(v0, v1);
                    uint32_t lo = pack_rn(v0 - trunc_bf(v0), v1 - trunc_bf(v1));
                    __nv_bfloat16* ah = (which == 0) ? g_qhi : (which == 1) ? g_khi : g_vhi;
                    __nv_bfloat16* al = (which == 0) ? g_qlo : (which == 1) ? g_klo : g_vlo;
                    size_t off = (((size_t)(m >> 9) * HH + h) * SS + (m & 511)) * EE + e;
                    *(uint32_t*)(ah + off) = hi;
                    *(uint32_t*)(al + off) = lo;
                } else {
                    float2 w; w.x = v0 + b0[n]; w.y = v1 + b0[n + 1];
                    *(float2*)(out + (size_t)m * DD + n) = w;
                }
            }
        }
    }
}

// ---------------------------------------------------------------------------
// Tensor-core flash attention, split-bf16 (3-term) QK^T and PV.
// grid (S/128, H, B); 256 threads = 8 warps; warp owns 16 q rows.
// KV tiles of 64, double-buffered cp.async.
// smem: QH 0, QL 16K | stage s at 32K+s*32K: KH+0, KL+8K, VH+16K, VL+24K
// ---------------------------------------------------------------------------
#define AT_SMEM (32768 + 2*32768)

__global__ __launch_bounds__(256) void attn_kernel()
{
    extern __shared__ char smem[];
    const uint32_t sb = smem_u32(smem);
    const int tid  = threadIdx.x;
    const int lane = tid & 31;
    const int w    = tid >> 5;

    const int qt = blockIdx.x, h = blockIdx.y, b = blockIdx.z;
    const size_t bh = (size_t)b * HH + h;

    const char* qh_g = (const char*)(g_qhi + (bh * SS + qt * 128) * EE);
    const char* ql_g = (const char*)(g_qlo + (bh * SS + qt * 128) * EE);
    const char* kh_g = (const char*)(g_khi + bh * SS * EE);
    const char* kl_g = (const char*)(g_klo + bh * SS * EE);
    const char* vh_g = (const char*)(g_vhi + bh * SS * EE);
    const char* vl_g = (const char*)(g_vlo + bh * SS * EE);

    // Q tiles: 128 rows x 128B each (hi & lo) = 1024 16B chunks each
    #pragma unroll
    for (int i = 0; i < 4; i++) {
        int idx = i * 256 + tid;
        int r = idx >> 3, c = idx & 7;
        cp16(sb + SW128(r * 128 + c * 16), qh_g + (size_t)r * 128 + c * 16);
        cp16(sb + 16384 + SW128(r * 128 + c * 16), ql_g + (size_t)r * 128 + c * 16);
    }

    auto load_kv = [&](int t, int s) {
        uint32_t kb = sb + 32768 + s * 32768;
        size_t rowbase = (size_t)t * 64 * 128;     // bytes
        #pragma unroll
        for (int i = 0; i < 8; i++) {
            int tile = i >> 1;
            int r = (i & 1) * 32 + (tid >> 3);
            int c = tid & 7;
            const char* src = (tile == 0) ? kh_g : (tile == 1) ? kl_g
                            : (tile == 2) ? vh_g : vl_g;
            cp16(kb + tile * 8192 + SW128(r * 128 + c * 16),
                 src + rowbase + (size_t)r * 128 + c * 16);
        }
    };

    load_kv(0, 0);
    cp_commit();

    float oacc[8][4];
    #pragma unroll
    for (int ni = 0; ni < 8; ni++)
        #pragma unroll
        for (int j = 0; j < 4; j++) oacc[ni][j] = 0.f;
    float m0 = -1e30f, m1 = -1e30f, l0 = 0.f, l1 = 0.f;

    uint32_t qh[4][4], ql[4][4];

    const int krow = (lane & 7) + ((lane >> 3) & 1) * 8;   // within 16-row group
    const int kch  = (lane >> 4) * 16;

    for (int t = 0; t < 8; t++) {
        cp_wait<0>();
        __syncthreads();

        if (t == 0) {
            // preload Q fragments (held in regs for whole loop)
            #pragma unroll
            for (int ks = 0; ks < 4; ks++) {
                uint32_t ad = SW128((w * 16 + (lane & 15)) * 128 + ks * 32 + (lane >> 4) * 16);
                ldsm4(qh[ks][0], qh[ks][1], qh[ks][2], qh[ks][3], sb + ad);
                ldsm4(ql[ks][0], ql[ks][1], ql[ks][2], ql[ks][3], sb + 16384 + ad);
            }
        }

        if (t < 7) { load_kv(t + 1, (t + 1) & 1); cp_commit(); }
        else       { cp_commit(); }

        uint32_t kb = sb + 32768 + (t & 1) * 32768;

        // ---- S = Q'K'^T (3 terms) ----
        float sacc[8][4];
        #pragma unroll
        for (int ni = 0; ni < 8; ni++)
            #pragma unroll
            for (int j = 0; j < 4; j++) sacc[ni][j] = 0.f;

        #pragma unroll
        for (int term = 0; term < 3; term++) {
            uint32_t kt = kb + ((term == 1) ? 8192 : 0);
            #pragma unroll
            for (int ks = 0; ks < 4; ks++) {
                uint32_t (&aq)[4] = (term == 2) ? ql[ks] : qh[ks];
                #pragma unroll
                for (int nj = 0; nj < 4; nj++) {
                    uint32_t r0, r1, r2, r3;
                    ldsm4(r0, r1, r2, r3,
                          kt + SW128((nj * 16 + krow) * 128 + ks * 32 + kch));
                    mma16816(sacc[2*nj][0], sacc[2*nj][1], sacc[2*nj][2], sacc[2*nj][3],
                             aq[0], aq[1], aq[2], aq[3], r0, r2);
                    mma16816(sacc[2*nj+1][0], sacc[2*nj+1][1], sacc[2*nj+1][2], sacc[2*nj+1][3],
                             aq[0], aq[1], aq[2], aq[3], r1, r3);
                }
            }
        }

        // ---- online softmax (warp-local rows) ----
        float ml0 = -1e30f, ml1 = -1e30f;
        #pragma unroll
        for (int ni = 0; ni < 8; ni++) {
            sacc[ni][0] *= 0.125f; sacc[ni][1] *= 0.125f;
            sacc[ni][2] *= 0.125f; sacc[ni][3] *= 0.125f;
            ml0 = fmaxf(ml0, fmaxf(sacc[ni][0], sacc[ni][1]));
            ml1 = fmaxf(ml1, fmaxf(sacc[ni][2], sacc[ni][3]));
        }
        ml0 = fmaxf(ml0, __shfl_xor_sync(0xffffffffu, ml0, 1));
        ml0 = fmaxf(ml0, __shfl_xor_sync(0xffffffffu, ml0, 2));
        ml1 = fmaxf(ml1, __shfl_xor_sync(0xffffffffu, ml1, 1));
        ml1 = fmaxf(ml1, __shfl_xor_sync(0xffffffffu, ml1, 2));

        float mn0 = fmaxf(m0, ml0), mn1 = fmaxf(m1, ml1);
        float corr0 = __expf(m0 - mn0), corr1 = __expf(m1 - mn1);
        m0 = mn0; m1 = mn1;

        float rs0 = 0.f, rs1 = 0.f;
        #pragma unroll
        for (int ni = 0; ni < 8; ni++) {
            sacc[ni][0] = __expf(sacc[ni][0] - mn0);
            sacc[ni][1] = __expf(sacc[ni][1] - mn0);
            sacc[ni][2] = __expf(sacc[ni][2] - mn1);
            sacc[ni][3] = __expf(sacc[ni][3] - mn1);
            rs0 += sacc[ni][0] + sacc[ni][1];
            rs1 += sacc[ni][2] + sacc[ni][3];
        }
        rs0 += __shfl_xor_sync(0xffffffffu, rs0, 1);
        rs0 += __shfl_xor_sync(0xffffffffu, rs0, 2);
        rs1 += __shfl_xor_sync(0xffffffffu, rs1, 1);
        rs1 += __shfl_xor_sync(0xffffffffu, rs1, 2);
        l0 = l0 * corr0 + rs0;
        l1 = l1 * corr1 + rs1;
        #pragma unroll
        for (int ni = 0; ni < 8; ni++) {
            oacc[ni][0] *= corr0; oacc[ni][1] *= corr0;
            oacc[ni][2] *= corr1; oacc[ni][3] *= corr1;
        }

        // ---- O += P'V' (3 terms), P fragments built from sacc registers ----
        #pragma unroll
        for (int ks = 0; ks < 4; ks++) {
            float* p0 = sacc[2 * ks];
            float* p1 = sacc[2 * ks + 1];
            uint32_t ah0 = pack_hi(p0[0], p0[1]);
            uint32_t ah1 = pack_hi(p0[2], p0[3]);
            uint32_t ah2 = pack_hi(p1[0], p1[1]);
            uint32_t ah3 = pack_hi(p1[2], p1[3]);
            uint32_t al0 = pack_rn(p0[0] - trunc_bf(p0[0]), p0[1] - trunc_bf(p0[1]));
            uint32_t al1 = pack_rn(p0[2] - trunc_bf(p0[2]), p0[3] - trunc_bf(p0[3]));
            uint32_t al2 = pack_rn(p1[0] - trunc_bf(p1[0]), p1[1] - trunc_bf(p1[1]));
            uint32_t al3 = pack_rn(p1[2] - trunc_bf(p1[2]), p1[3] - trunc_bf(p1[3]));
            #pragma unroll
            for (int ep = 0; ep < 4; ep++) {
                uint32_t ad = SW128((ks * 16 + krow) * 128 + ep * 32 + kch);
                uint32_t vh0, vh1, vh2, vh3, vl0_, vl1_, vl2_, vl3_;
                ldsm4t(vh0, vh1, vh2, vh3, kb + 16384 + ad);
                ldsm4t(vl0_, vl1_, vl2_, vl3_, kb + 24576 + ad);
                // (phi, vhi)
                mma16816(oacc[2*ep][0], oacc[2*ep][1], oacc[2*ep][2], oacc[2*ep][3],
                         ah0, ah1, ah2, ah3, vh0, vh1);
                mma16816(oacc[2*ep+1][0], oacc[2*ep+1][1], oacc[2*ep+1][2], oacc[2*ep+1][3],
                         ah0, ah1, ah2, ah3, vh2, vh3);
                // (phi, vlo)
                mma16816(oacc[2*ep][0], oacc[2*ep][1], oacc[2*ep][2], oacc[2*ep][3],
                         ah0, ah1, ah2, ah3, vl0_, vl1_);
                mma16816(oacc[2*ep+1][0], oacc[2*ep+1][1], oacc[2*ep+1][2], oacc[2*ep+1][3],
                         ah0, ah1, ah2, ah3, vl2_, vl3_);
                // (plo, vhi)
                mma16816(oacc[2*ep][0], oacc[2*ep][1], oacc[2*ep][2], oacc[2*ep][3],
                         al0, al1, al2, al3, vh0, vh1);
                mma16816(oacc[2*ep+1][0], oacc[2*ep+1][1], oacc[2*ep+1][2], oacc[2*ep+1][3],
                         al0, al1, al2, al3, vh2, vh3);
            }
        }
    }

    // ---- epilogue: normalize + write split rows into g_as ----
    float inv0 = 1.f / l0, inv1 = 1.f / l1;
    int mrow = b * SS + qt * 128 + w * 16 + (lane >> 2);
    int colb = h * 64 + (lane & 3) * 2;
    #pragma unroll
    for (int ni = 0; ni < 8; ni++) {
        float v0 = oacc[ni][0] * inv0, v1 = oacc[ni][1] * inv0;
        float v2 = oacc[ni][2] * inv1, v3 = oacc[ni][3] * inv1;
        size_t base0 = (size_t)mrow * K2 + colb + ni * 8;
        size_t base1 = (size_t)(mrow + 8) * K2 + colb + ni * 8;
        uint32_t h0 = pack_hi(v0, v1);
        uint32_t l0p = pack_rn(v0 - trunc_bf(v0), v1 - trunc_bf(v1));
        uint32_t h1 = pack_hi(v2, v3);
        uint32_t l1p = pack_rn(v2 - trunc_bf(v2), v3 - trunc_bf(v3));
        *(uint32_t*)(g_as + base0)          = h0;
        *(uint32_t*)(g_as + base0 + DD)     = h0;
        *(uint32_t*)(g_as + base0 + 2*DD)   = l0p;
        *(uint32_t*)(g_as + base1)          = h1;
        *(uint32_t*)(g_as + base1 + DD)     = h1;
        *(uint32_t*)(g_as + base1 + 2*DD)   = l1p;
    }
}

// ---------------------------------------------------------------------------
extern "C" void kernel_launch(void* const* d_in, const int* in_sizes, int n_in,
                              void* d_out, int out_size)
{
    const float* x  = (const float*)d_in[0];
    const float* Wq = (const float*)d_in[1];
    const float* Wk = (const float*)d_in[2];
    const float* Wv = (const float*)d_in[3];
    const float* bq = (const float*)d_in[4];
    const float* bk = (const float*)d_in[5];
    const float* bv = (const float*)d_in[6];
    const float* Wo = (const float*)d_in[7];
    const float* bo = (const float*)d_in[8];
    float* out = (float*)d_out;

    cudaFuncSetAttribute(gemm_kernel, cudaFuncAttributeMaxDynamicSharedMemorySize, SMEM_TOTAL);
    cudaFuncSetAttribute(attn_kernel, cudaFuncAttributeMaxDynamicSharedMemorySize, AT_SMEM);

    prep_x<<<(M_TOT * DD + 255) / 256, 256>>>(x);
    prep_wqkv<<<(N_QKV * DD + 255) / 256, 256>>>(Wq, Wk, Wv);
    prep_wo<<<(DD * DD + 255) / 256, 256>>>(Wo);

    gemm_kernel<<<dim3(N_QKV / TBN, M_TOT / TBM), 256, SMEM_TOTAL>>>(
        0, bq, bk, bv, nullptr);

    attn_kernel<<<dim3(SS / 128, HH, BB), 256, AT_SMEM>>>();

    gemm_kernel<<<dim3(DD / TBN, M_TOT / TBM), 256, SMEM_TOTAL>>>(
        1, bo, bo, bo, out);
}

// round 6
// speedup vs baseline: 2.8431x; 1.0062x over previous
#include <cuda_runtime.h>
#include <cuda_bf16.h>
#include <math.h>
#include <stdint.h>

#define BB 32
#define SS 512
#define DD 768
#define HH 12
#define EE 64

#define M_TOT (BB*SS)        // 16384
#define N_QKV (3*DD)         // 2304
#define K2    (3*DD)         // split-K: A'=[hi|hi|lo], B'=[hi|lo|hi]

#define TBM 128
#define TBN 128
#define TBK 64
#define NSTAGE 3
#define STAGE_BYTES (2*TBM*TBK*2)            // 32KB
#define SMEM_TOTAL (NSTAGE*STAGE_BYTES)      // 96KB
#define NKT (K2/TBK)         // 36

// ---------------- device scratch ----------------
__device__ __nv_bfloat16 g_xs[M_TOT*K2];      // x split  [m][k']
__device__ __nv_bfloat16 g_as[M_TOT*K2];      // attn-out split [m][k']
__device__ __nv_bfloat16 g_wqkvs[N_QKV*K2];   // qkv weights split [n][k']
__device__ __nv_bfloat16 g_wos[DD*K2];        // Wo^T split [n][k']
__device__ __nv_bfloat16 g_qhi[BB*HH*SS*EE];  // [B,H,S,E]
__device__ __nv_bfloat16 g_qlo[BB*HH*SS*EE];
__device__ __nv_bfloat16 g_khi[BB*HH*SS*EE];
__device__ __nv_bfloat16 g_klo[BB*HH*SS*EE];
__device__ __nv_bfloat16 g_vhi[BB*HH*SS*EE];
__device__ __nv_bfloat16 g_vlo[BB*HH*SS*EE];

// ---------------- helpers ----------------
#define SW128(o) ((o) ^ (((o) >> 3) & 0x70))

__device__ __forceinline__ uint32_t smem_u32(const void* p) {
    return (uint32_t)__cvta_generic_to_shared(p);
}
__device__ __forceinline__ void cp16(uint32_t dst, const void* src) {
    asm volatile("cp.async.cg.shared.global [%0], [%1], 16;" :: "r"(dst), "l"(src) : "memory");
}
__device__ __forceinline__ void cp_commit() {
    asm volatile("cp.async.commit_group;" ::: "memory");
}
template <int N> __device__ __forceinline__ void cp_wait() {
    asm volatile("cp.async.wait_group %0;" :: "n"(N) : "memory");
}
__device__ __forceinline__ void ldsm4(uint32_t& a, uint32_t& b, uint32_t& c, uint32_t& d,
                                      uint32_t addr) {
    asm volatile("ldmatrix.sync.aligned.m8n8.x4.shared.b16 {%0,%1,%2,%3}, [%4];"
                 : "=r"(a), "=r"(b), "=r"(c), "=r"(d) : "r"(addr));
}
__device__ __forceinline__ void ldsm4t(uint32_t& a, uint32_t& b, uint32_t& c, uint32_t& d,
                                       uint32_t addr) {
    asm volatile("ldmatrix.sync.aligned.m8n8.x4.trans.shared.b16 {%0,%1,%2,%3}, [%4];"
                 : "=r"(a), "=r"(b), "=r"(c), "=r"(d) : "r"(addr));
}
__device__ __forceinline__ void mma16816(float& c0, float& c1, float& c2, float& c3,
                                         uint32_t a0, uint32_t a1, uint32_t a2, uint32_t a3,
                                         uint32_t b0, uint32_t b1) {
    asm volatile(
        "mma.sync.aligned.m16n8k16.row.col.f32.bf16.bf16.f32 "
        "{%0,%1,%2,%3}, {%4,%5,%6,%7}, {%8,%9}, {%0,%1,%2,%3};"
        : "+f"(c0), "+f"(c1), "+f"(c2), "+f"(c3)
        : "r"(a0), "r"(a1), "r"(a2), "r"(a3), "r"(b0), "r"(b1));
}
__device__ __forceinline__ uint32_t pack_hi(float v0, float v1) {
    return __byte_perm(__float_as_uint(v0), __float_as_uint(v1), 0x7632);
}
__device__ __forceinline__ float trunc_bf(float v) {
    return __uint_as_float(__float_as_uint(v) & 0xffff0000u);
}
__device__ __forceinline__ uint32_t pack_rn(float l0, float l1) {
    uint32_t r;
    asm("cvt.rn.bf16x2.f32 %0, %1, %2;" : "=r"(r) : "f"(l1), "f"(l0));
    return r;
}

// ---------------------------------------------------------------------------
// prep kernels
// ---------------------------------------------------------------------------
__global__ void prep_x(const float* __restrict__ x) {
    int i = blockIdx.x * 256 + threadIdx.x;
    if (i >= M_TOT * DD) return;
    int m = i / DD, k = i - (i / DD) * DD;
    float v = x[i];
    __nv_bfloat16 h = __float2bfloat16(v);
    __nv_bfloat16 l = __float2bfloat16(v - __bfloat162float(h));
    size_t base = (size_t)m * K2 + k;
    g_xs[base]          = h;
    g_xs[base + DD]     = h;
    g_xs[base + 2 * DD] = l;
}
__global__ void prep_wqkv(const float* __restrict__ Wq, const float* __restrict__ Wk,
                          const float* __restrict__ Wv) {
    int i = blockIdx.x * 256 + threadIdx.x;
    if (i >= N_QKV * DD) return;
    int n = i / DD, k = i - (i / DD) * DD;
    int which = n / DD;
    int rem = n - which * DD;
    int h = rem >> 6, e = rem & 63;
    const float* W = (which == 0) ? Wq : (which == 1) ? Wk : Wv;
    float v = W[((size_t)h * DD + k) * EE + e];
    __nv_bfloat16 hv = __float2bfloat16(v);
    __nv_bfloat16 lv = __float2bfloat16(v - __bfloat162float(hv));
    size_t base = (size_t)n * K2 + k;
    g_wqkvs[base]          = hv;
    g_wqkvs[base + DD]     = lv;
    g_wqkvs[base + 2 * DD] = hv;
}
__global__ void prep_wo(const float* __restrict__ Wo) {
    int i = blockIdx.x * 256 + threadIdx.x;
    if (i >= DD * DD) return;
    int n = i / DD, k = i - (i / DD) * DD;
    float v = Wo[(size_t)k * DD + n];
    __nv_bfloat16 hv = __float2bfloat16(v);
    __nv_bfloat16 lv = __float2bfloat16(v - __bfloat162float(hv));
    size_t base = (size_t)n * K2 + k;
    g_wos[base]          = hv;
    g_wos[base + DD]     = lv;
    g_wos[base + 2 * DD] = hv;
}

// ---------------------------------------------------------------------------
// bf16 mma.sync GEMM: 128x128 block, 128 threads (2x2 warps, warp tile 64x64),
// 3-stage cp.async, ks-level fragment double buffering.
// ---------------------------------------------------------------------------
__global__ __launch_bounds__(128) void gemm_kernel(
    int mode, const float* __restrict__ b0, const float* __restrict__ b1,
    const float* __restrict__ b2, float* __restrict__ out)
{
    extern __shared__ char smem[];
    const uint32_t sbase = smem_u32(smem);
    const int tid  = threadIdx.x;
    const int lane = tid & 31;
    const int warp = tid >> 5;
    const int wm = warp >> 1;        // 0..1
    const int wn = warp & 1;         // 0..1

    const int bn = blockIdx.x, bm = blockIdx.y;

    const __nv_bfloat16* A  = mode ? g_as : g_xs;
    const __nv_bfloat16* Bw = mode ? g_wos : g_wqkvs;
    const char* Abase = (const char*)(A  + (size_t)bm * TBM * K2);
    const char* Bbase = (const char*)(Bw + (size_t)bn * TBN * K2);

    auto load_stage = [&](int kt, int s) {
        uint32_t sb = sbase + s * STAGE_BYTES;
        size_t kb = (size_t)kt * (TBK * 2);
        #pragma unroll
        for (int i = 0; i < 8; i++) {
            int idx = i * 128 + tid;
            int r = idx >> 3, c = idx & 7;
            cp16(sb + SW128(r * 128 + c * 16),
                 Abase + (size_t)r * (K2 * 2) + kb + c * 16);
        }
        #pragma unroll
        for (int i = 0; i < 8; i++) {
            int idx = i * 128 + tid;
            int r = idx >> 3, c = idx & 7;
            cp16(sb + 16384 + SW128(r * 128 + c * 16),
                 Bbase + (size_t)r * (K2 * 2) + kb + c * 16);
        }
        cp_commit();
    };

    float acc[4][8][4];
    #pragma unroll
    for (int mi = 0; mi < 4; mi++)
        #pragma unroll
        for (int ni = 0; ni < 8; ni++)
            #pragma unroll
            for (int j = 0; j < 4; j++) acc[mi][ni][j] = 0.f;

    load_stage(0, 0);
    load_stage(1, 1);

    const int a_row = wm * 64 + (lane & 15);
    const int a_chb = (lane >> 4) * 16;                      // byte offset in chunk
    const int b_row = wn * 64 + (lane & 7) + ((lane >> 3) & 1) * 8;
    const int b_chb = (lane >> 4) * 16;

    uint32_t afr[2][4][4];
    uint32_t bfr[2][8][2];

    auto ldfr = [&](int ks, uint32_t sb, int buf) {
        #pragma unroll
        for (int mi = 0; mi < 4; mi++)
            ldsm4(afr[buf][mi][0], afr[buf][mi][1], afr[buf][mi][2], afr[buf][mi][3],
                  sb + SW128((a_row + mi * 16) * 128 + ks * 32 + a_chb));
        #pragma unroll
        for (int p = 0; p < 4; p++) {
            uint32_t r0, r1, r2, r3;
            ldsm4(r0, r1, r2, r3,
                  sb + 16384 + SW128((b_row + p * 16) * 128 + ks * 32 + b_chb));
            bfr[buf][2 * p + 0][0] = r0; bfr[buf][2 * p + 0][1] = r2;
            bfr[buf][2 * p + 1][0] = r1; bfr[buf][2 * p + 1][1] = r3;
        }
    };

    for (int kt = 0; kt < NKT; kt++) {
        cp_wait<NSTAGE - 2>();
        __syncthreads();

        if (kt + NSTAGE - 1 < NKT)
            load_stage(kt + NSTAGE - 1, (kt + NSTAGE - 1) % NSTAGE);
        else
            cp_commit();

        uint32_t sb = sbase + (kt % NSTAGE) * STAGE_BYTES;

        ldfr(0, sb, 0);
        #pragma unroll
        for (int ks = 0; ks < 4; ks++) {
            if (ks < 3) ldfr(ks + 1, sb, (ks + 1) & 1);
            int cur = ks & 1;
            #pragma unroll
            for (int mi = 0; mi < 4; mi++)
                #pragma unroll
                for (int ni = 0; ni < 8; ni++)
                    mma16816(acc[mi][ni][0], acc[mi][ni][1], acc[mi][ni][2], acc[mi][ni][3],
                             afr[cur][mi][0], afr[cur][mi][1], afr[cur][mi][2], afr[cur][mi][3],
                             bfr[cur][ni][0], bfr[cur][ni][1]);
        }
        __syncthreads();
    }

    const int gid = lane >> 2;
    const int tg  = lane & 3;
    #pragma unroll
    for (int mi = 0; mi < 4; mi++) {
        #pragma unroll
        for (int half = 0; half < 2; half++) {
            int m = bm * TBM + wm * 64 + mi * 16 + gid + half * 8;
            #pragma unroll
            for (int ni = 0; ni < 8; ni++) {
                int n = bn * TBN + wn * 64 + ni * 8 + tg * 2;
                float v0 = acc[mi][ni][half * 2 + 0];
                float v1 = acc[mi][ni][half * 2 + 1];
                if (mode == 0) {
                    int which = n / DD;
                    int rem = n - which * DD;
                    int h = rem >> 6, e = rem & 63;
                    const float* bp = ((which == 0) ? b0 : (which == 1) ? b1 : b2) + h * EE + e;
                    v0 += bp[0]; v1 += bp[1];
                    uint32_t hi = pack_hi(v0, v1);
                    uint32_t lo = pack_rn(v0 - trunc_bf(v0), v1 - trunc_bf(v1));
                    __nv_bfloat16* ah = (which == 0) ? g_qhi : (which == 1) ? g_khi : g_vhi;
                    __nv_bfloat16* al = (which == 0) ? g_qlo : (which == 1) ? g_klo : g_vlo;
                    size_t off = (((size_t)(m >> 9) * HH + h) * SS + (m & 511)) * EE + e;
                    *(uint32_t*)(ah + off) = hi;
                    *(uint32_t*)(al + off) = lo;
                } else {
                    float2 w; w.x = v0 + b0[n]; w.y = v1 + b0[n + 1];
                    *(float2*)(out + (size_t)m * DD + n) = w;
                }
            }
        }
    }
}

// ---------------------------------------------------------------------------
// Tensor-core flash attention, split-bf16 (3-term) QK^T and PV.
// grid (S/128, H, B); 256 threads = 8 warps; warp owns 16 q rows.
// KV tiles of 64, double-buffered cp.async.
// smem: QH 0, QL 16K | stage s at 32K+s*32K: KH+0, KL+8K, VH+16K, VL+24K
// ---------------------------------------------------------------------------
#define AT_SMEM (32768 + 2*32768)

__global__ __launch_bounds__(256) void attn_kernel()
{
    extern __shared__ char smem[];
    const uint32_t sb = smem_u32(smem);
    const int tid  = threadIdx.x;
    const int lane = tid & 31;
    const int w    = tid >> 5;

    const int qt = blockIdx.x, h = blockIdx.y, b = blockIdx.z;
    const size_t bh = (size_t)b * HH + h;

    const char* qh_g = (const char*)(g_qhi + (bh * SS + qt * 128) * EE);
    const char* ql_g = (const char*)(g_qlo + (bh * SS + qt * 128) * EE);
    const char* kh_g = (const char*)(g_khi + bh * SS * EE);
    const char* kl_g = (const char*)(g_klo + bh * SS * EE);
    const char* vh_g = (const char*)(g_vhi + bh * SS * EE);
    const char* vl_g = (const char*)(g_vlo + bh * SS * EE);

    // Q tiles: 128 rows x 128B each (hi & lo) = 1024 16B chunks each
    #pragma unroll
    for (int i = 0; i < 4; i++) {
        int idx = i * 256 + tid;
        int r = idx >> 3, c = idx & 7;
        cp16(sb + SW128(r * 128 + c * 16), qh_g + (size_t)r * 128 + c * 16);
        cp16(sb + 16384 + SW128(r * 128 + c * 16), ql_g + (size_t)r * 128 + c * 16);
    }

    auto load_kv = [&](int t, int s) {
        uint32_t kb = sb + 32768 + s * 32768;
        size_t rowbase = (size_t)t * 64 * 128;     // bytes
        #pragma unroll
        for (int i = 0; i < 8; i++) {
            int tile = i >> 1;
            int r = (i & 1) * 32 + (tid >> 3);
            int c = tid & 7;
            const char* src = (tile == 0) ? kh_g : (tile == 1) ? kl_g
                            : (tile == 2) ? vh_g : vl_g;
            cp16(kb + tile * 8192 + SW128(r * 128 + c * 16),
                 src + rowbase + (size_t)r * 128 + c * 16);
        }
    };

    load_kv(0, 0);
    cp_commit();

    float oacc[8][4];
    #pragma unroll
    for (int ni = 0; ni < 8; ni++)
        #pragma unroll
        for (int j = 0; j < 4; j++) oacc[ni][j] = 0.f;
    float m0 = -1e30f, m1 = -1e30f, l0 = 0.f, l1 = 0.f;

    uint32_t qh[4][4], ql[4][4];

    const int krow = (lane & 7) + ((lane >> 3) & 1) * 8;   // within 16-row group
    const int kch  = (lane >> 4) * 16;

    for (int t = 0; t < 8; t++) {
        cp_wait<0>();
        __syncthreads();

        if (t == 0) {
            // preload Q fragments (held in regs for whole loop)
            #pragma unroll
            for (int ks = 0; ks < 4; ks++) {
                uint32_t ad = SW128((w * 16 + (lane & 15)) * 128 + ks * 32 + (lane >> 4) * 16);
                ldsm4(qh[ks][0], qh[ks][1], qh[ks][2], qh[ks][3], sb + ad);
                ldsm4(ql[ks][0], ql[ks][1], ql[ks][2], ql[ks][3], sb + 16384 + ad);
            }
        }

        if (t < 7) { load_kv(t + 1, (t + 1) & 1); cp_commit(); }
        else       { cp_commit(); }

        uint32_t kb = sb + 32768 + (t & 1) * 32768;

        // ---- S = Q'K'^T (3 terms, K frags loaded once) ----
        float sacc[8][4];
        #pragma unroll
        for (int ni = 0; ni < 8; ni++)
            #pragma unroll
            for (int j = 0; j < 4; j++) sacc[ni][j] = 0.f;

        #pragma unroll
        for (int ks = 0; ks < 4; ks++) {
            #pragma unroll
            for (int nj = 0; nj < 4; nj++) {
                uint32_t ad = SW128((nj * 16 + krow) * 128 + ks * 32 + kch);
                uint32_t h0, h1, h2, h3, e0, e1, e2, e3;
                ldsm4(h0, h1, h2, h3, kb + ad);           // K hi
                ldsm4(e0, e1, e2, e3, kb + 8192 + ad);    // K lo
                // qh . kh
                mma16816(sacc[2*nj][0], sacc[2*nj][1], sacc[2*nj][2], sacc[2*nj][3],
                         qh[ks][0], qh[ks][1], qh[ks][2], qh[ks][3], h0, h2);
                mma16816(sacc[2*nj+1][0], sacc[2*nj+1][1], sacc[2*nj+1][2], sacc[2*nj+1][3],
                         qh[ks][0], qh[ks][1], qh[ks][2], qh[ks][3], h1, h3);
                // qh . kl
                mma16816(sacc[2*nj][0], sacc[2*nj][1], sacc[2*nj][2], sacc[2*nj][3],
                         qh[ks][0], qh[ks][1], qh[ks][2], qh[ks][3], e0, e2);
                mma16816(sacc[2*nj+1][0], sacc[2*nj+1][1], sacc[2*nj+1][2], sacc[2*nj+1][3],
                         qh[ks][0], qh[ks][1], qh[ks][2], qh[ks][3], e1, e3);
                // ql . kh
                mma16816(sacc[2*nj][0], sacc[2*nj][1], sacc[2*nj][2], sacc[2*nj][3],
                         ql[ks][0], ql[ks][1], ql[ks][2], ql[ks][3], h0, h2);
                mma16816(sacc[2*nj+1][0], sacc[2*nj+1][1], sacc[2*nj+1][2], sacc[2*nj+1][3],
                         ql[ks][0], ql[ks][1], ql[ks][2], ql[ks][3], h1, h3);
            }
        }

        // ---- online softmax (warp-local rows) ----
        float ml0 = -1e30f, ml1 = -1e30f;
        #pragma unroll
        for (int ni = 0; ni < 8; ni++) {
            sacc[ni][0] *= 0.125f; sacc[ni][1] *= 0.125f;
            sacc[ni][2] *= 0.125f; sacc[ni][3] *= 0.125f;
            ml0 = fmaxf(ml0, fmaxf(sacc[ni][0], sacc[ni][1]));
            ml1 = fmaxf(ml1, fmaxf(sacc[ni][2], sacc[ni][3]));
        }
        ml0 = fmaxf(ml0, __shfl_xor_sync(0xffffffffu, ml0, 1));
        ml0 = fmaxf(ml0, __shfl_xor_sync(0xffffffffu, ml0, 2));
        ml1 = fmaxf(ml1, __shfl_xor_sync(0xffffffffu, ml1, 1));
        ml1 = fmaxf(ml1, __shfl_xor_sync(0xffffffffu, ml1, 2));

        float mn0 = fmaxf(m0, ml0), mn1 = fmaxf(m1, ml1);
        float corr0 = __expf(m0 - mn0), corr1 = __expf(m1 - mn1);
        m0 = mn0; m1 = mn1;

        float rs0 = 0.f, rs1 = 0.f;
        #pragma unroll
        for (int ni = 0; ni < 8; ni++) {
            sacc[ni][0] = __expf(sacc[ni][0] - mn0);
            sacc[ni][1] = __expf(sacc[ni][1] - mn0);
            sacc[ni][2] = __expf(sacc[ni][2] - mn1);
            sacc[ni][3] = __expf(sacc[ni][3] - mn1);
            rs0 += sacc[ni][0] + sacc[ni][1];
            rs1 += sacc[ni][2] + sacc[ni][3];
        }
        rs0 += __shfl_xor_sync(0xffffffffu, rs0, 1);
        rs0 += __shfl_xor_sync(0xffffffffu, rs0, 2);
        rs1 += __shfl_xor_sync(0xffffffffu, rs1, 1);
        rs1 += __shfl_xor_sync(0xffffffffu, rs1, 2);
        l0 = l0 * corr0 + rs0;
        l1 = l1 * corr1 + rs1;
        #pragma unroll
        for (int ni = 0; ni < 8; ni++) {
            oacc[ni][0] *= corr0; oacc[ni][1] *= corr0;
            oacc[ni][2] *= corr1; oacc[ni][3] *= corr1;
        }

        // ---- O += P'V' (3 terms), P fragments built from sacc registers ----
        #pragma unroll
        for (int ks = 0; ks < 4; ks++) {
            float* p0 = sacc[2 * ks];
            float* p1 = sacc[2 * ks + 1];
            uint32_t ah0 = pack_hi(p0[0], p0[1]);
            uint32_t ah1 = pack_hi(p0[2], p0[3]);
            uint32_t ah2 = pack_hi(p1[0], p1[1]);
            uint32_t ah3 = pack_hi(p1[2], p1[3]);
            uint32_t al0 = pack_rn(p0[0] - trunc_bf(p0[0]), p0[1] - trunc_bf(p0[1]));
            uint32_t al1 = pack_rn(p0[2] - trunc_bf(p0[2]), p0[3] - trunc_bf(p0[3]));
            uint32_t al2 = pack_rn(p1[0] - trunc_bf(p1[0]), p1[1] - trunc_bf(p1[1]));
            uint32_t al3 = pack_rn(p1[2] - trunc_bf(p1[2]), p1[3] - trunc_bf(p1[3]));
            #pragma unroll
            for (int ep = 0; ep < 4; ep++) {
                uint32_t ad = SW128((ks * 16 + krow) * 128 + ep * 32 + kch);
                uint32_t vh0, vh1, vh2, vh3, vl0_, vl1_, vl2_, vl3_;
                ldsm4t(vh0, vh1, vh2, vh3, kb + 16384 + ad);
                ldsm4t(vl0_, vl1_, vl2_, vl3_, kb + 24576 + ad);
                mma16816(oacc[2*ep][0], oacc[2*ep][1], oacc[2*ep][2], oacc[2*ep][3],
                         ah0, ah1, ah2, ah3, vh0, vh1);
                mma16816(oacc[2*ep+1][0], oacc[2*ep+1][1], oacc[2*ep+1][2], oacc[2*ep+1][3],
                         ah0, ah1, ah2, ah3, vh2, vh3);
                mma16816(oacc[2*ep][0], oacc[2*ep][1], oacc[2*ep][2], oacc[2*ep][3],
                         ah0, ah1, ah2, ah3, vl0_, vl1_);
                mma16816(oacc[2*ep+1][0], oacc[2*ep+1][1], oacc[2*ep+1][2], oacc[2*ep+1][3],
                         ah0, ah1, ah2, ah3, vl2_, vl3_);
                mma16816(oacc[2*ep][0], oacc[2*ep][1], oacc[2*ep][2], oacc[2*ep][3],
                         al0, al1, al2, al3, vh0, vh1);
                mma16816(oacc[2*ep+1][0], oacc[2*ep+1][1], oacc[2*ep+1][2], oacc[2*ep+1][3],
                         al0, al1, al2, al3, vh2, vh3);
            }
        }
    }

    // ---- epilogue: normalize + write split rows into g_as ----
    float inv0 = 1.f / l0, inv1 = 1.f / l1;
    int mrow = b * SS + qt * 128 + w * 16 + (lane >> 2);
    int colb = h * 64 + (lane & 3) * 2;
    #pragma unroll
    for (int ni = 0; ni < 8; ni++) {
        float v0 = oacc[ni][0] * inv0, v1 = oacc[ni][1] * inv0;
        float v2 = oacc[ni][2] * inv1, v3 = oacc[ni][3] * inv1;
        size_t base0 = (size_t)mrow * K2 + colb + ni * 8;
        size_t base1 = (size_t)(mrow + 8) * K2 + colb + ni * 8;
        uint32_t h0 = pack_hi(v0, v1);
        uint32_t l0p = pack_rn(v0 - trunc_bf(v0), v1 - trunc_bf(v1));
        uint32_t h1 = pack_hi(v2, v3);
        uint32_t l1p = pack_rn(v2 - trunc_bf(v2), v3 - trunc_bf(v3));
        *(uint32_t*)(g_as + base0)          = h0;
        *(uint32_t*)(g_as + base0 + DD)     = h0;
        *(uint32_t*)(g_as + base0 + 2*DD)   = l0p;
        *(uint32_t*)(g_as + base1)          = h1;
        *(uint32_t*)(g_as + base1 + DD)     = h1;
        *(uint32_t*)(g_as + base1 + 2*DD)   = l1p;
    }
}

// ---------------------------------------------------------------------------
extern "C" void kernel_launch(void* const* d_in, const int* in_sizes, int n_in,
                              void* d_out, int out_size)
{
    const float* x  = (const float*)d_in[0];
    const float* Wq = (const float*)d_in[1];
    const float* Wk = (const float*)d_in[2];
    const float* Wv = (const float*)d_in[3];
    const float* bq = (const float*)d_in[4];
    const float* bk = (const float*)d_in[5];
    const float* bv = (const float*)d_in[6];
    const float* Wo = (const float*)d_in[7];
    const float* bo = (const float*)d_in[8];
    float* out = (float*)d_out;

    cudaFuncSetAttribute(gemm_kernel, cudaFuncAttributeMaxDynamicSharedMemorySize, SMEM_TOTAL);
    cudaFuncSetAttribute(attn_kernel, cudaFuncAttributeMaxDynamicSharedMemorySize, AT_SMEM);

    prep_x<<<(M_TOT * DD + 255) / 256, 256>>>(x);
    prep_wqkv<<<(N_QKV * DD + 255) / 256, 256>>>(Wq, Wk, Wv);
    prep_wo<<<(DD * DD + 255) / 256, 256>>>(Wo);

    gemm_kernel<<<dim3(N_QKV / TBN, M_TOT / TBM), 128, SMEM_TOTAL>>>(
        0, bq, bk, bv, nullptr);

    attn_kernel<<<dim3(SS / 128, HH, BB), 256, AT_SMEM>>>();

    gemm_kernel<<<dim3(DD / TBN, M_TOT / TBM), 128, SMEM_TOTAL>>>(
        1, bo, bo, bo, out);
}

// round 7
// speedup vs baseline: 2.9076x; 1.0227x over previous
#include <cuda_runtime.h>
#include <cuda_bf16.h>
#include <math.h>
#include <stdint.h>

#define BB 32
#define SS 512
#define DD 768
#define HH 12
#define EE 64

#define M_TOT (BB*SS)        // 16384
#define N_QKV (3*DD)         // 2304
#define NKC   (DD/64)        // 12 base-k chunks of 64

// GEMM tiling: 256x128 CTA tile, 8 warps (4x2), warp tile 64x64, 2-stage
#define S_AHI 0
#define S_ALO 32768
#define S_BHI 65536
#define S_BLO 81920
#define STG   98304          // 96KB per stage
#define G_SMEM (2*STG)       // 192KB

// ---------------- device scratch ----------------
__device__ __nv_bfloat16 g_xhi[M_TOT*DD],  g_xlo[M_TOT*DD];    // x split
__device__ __nv_bfloat16 g_ashi[M_TOT*DD], g_aslo[M_TOT*DD];   // attn out split
__device__ __nv_bfloat16 g_wqhi[N_QKV*DD], g_wqlo[N_QKV*DD];   // qkv W^T split
__device__ __nv_bfloat16 g_wohi[DD*DD],    g_wolo[DD*DD];      // Wo^T split
__device__ __nv_bfloat16 g_qhi[BB*HH*SS*EE], g_qlo[BB*HH*SS*EE];
__device__ __nv_bfloat16 g_khi[BB*HH*SS*EE], g_klo[BB*HH*SS*EE];
__device__ __nv_bfloat16 g_vhi[BB*HH*SS*EE], g_vlo[BB*HH*SS*EE];

// ---------------- helpers ----------------
#define SW128(o) ((o) ^ (((o) >> 3) & 0x70))

__device__ __forceinline__ uint32_t smem_u32(const void* p) {
    return (uint32_t)__cvta_generic_to_shared(p);
}
__device__ __forceinline__ void cp16(uint32_t dst, const void* src) {
    asm volatile("cp.async.cg.shared.global [%0], [%1], 16;" :: "r"(dst), "l"(src) : "memory");
}
__device__ __forceinline__ void cp_commit() {
    asm volatile("cp.async.commit_group;" ::: "memory");
}
template <int N> __device__ __forceinline__ void cp_wait() {
    asm volatile("cp.async.wait_group %0;" :: "n"(N) : "memory");
}
__device__ __forceinline__ void ldsm4(uint32_t& a, uint32_t& b, uint32_t& c, uint32_t& d,
                                      uint32_t addr) {
    asm volatile("ldmatrix.sync.aligned.m8n8.x4.shared.b16 {%0,%1,%2,%3}, [%4];"
                 : "=r"(a), "=r"(b), "=r"(c), "=r"(d) : "r"(addr));
}
__device__ __forceinline__ void ldsm4t(uint32_t& a, uint32_t& b, uint32_t& c, uint32_t& d,
                                       uint32_t addr) {
    asm volatile("ldmatrix.sync.aligned.m8n8.x4.trans.shared.b16 {%0,%1,%2,%3}, [%4];"
                 : "=r"(a), "=r"(b), "=r"(c), "=r"(d) : "r"(addr));
}
__device__ __forceinline__ void mma16816(float& c0, float& c1, float& c2, float& c3,
                                         uint32_t a0, uint32_t a1, uint32_t a2, uint32_t a3,
                                         uint32_t b0, uint32_t b1) {
    asm volatile(
        "mma.sync.aligned.m16n8k16.row.col.f32.bf16.bf16.f32 "
        "{%0,%1,%2,%3}, {%4,%5,%6,%7}, {%8,%9}, {%0,%1,%2,%3};"
        : "+f"(c0), "+f"(c1), "+f"(c2), "+f"(c3)
        : "r"(a0), "r"(a1), "r"(a2), "r"(a3), "r"(b0), "r"(b1));
}
__device__ __forceinline__ uint32_t pack_hi(float v0, float v1) {
    return __byte_perm(__float_as_uint(v0), __float_as_uint(v1), 0x7632);
}
__device__ __forceinline__ float trunc_bf(float v) {
    return __uint_as_float(__float_as_uint(v) & 0xffff0000u);
}
__device__ __forceinline__ uint32_t pack_rn(float l0, float l1) {
    uint32_t r;
    asm("cvt.rn.bf16x2.f32 %0, %1, %2;" : "=r"(r) : "f"(l1), "f"(l0));
    return r;
}

// ---------------------------------------------------------------------------
// prep kernels: fp32 -> separate hi/lo bf16 arrays
// ---------------------------------------------------------------------------
__global__ void prep_x(const float* __restrict__ x) {
    int i = blockIdx.x * 256 + threadIdx.x;
    if (i >= M_TOT * DD) return;
    float v = x[i];
    __nv_bfloat16 h = __float2bfloat16(v);
    g_xhi[i] = h;
    g_xlo[i] = __float2bfloat16(v - __bfloat162float(h));
}
__global__ void prep_wqkv(const float* __restrict__ Wq, const float* __restrict__ Wk,
                          const float* __restrict__ Wv) {
    int i = blockIdx.x * 256 + threadIdx.x;
    if (i >= N_QKV * DD) return;
    int n = i / DD, k = i - (i / DD) * DD;
    int which = n / DD;
    int rem = n - which * DD;
    int h = rem >> 6, e = rem & 63;
    const float* W = (which == 0) ? Wq : (which == 1) ? Wk : Wv;
    float v = W[((size_t)h * DD + k) * EE + e];
    __nv_bfloat16 hv = __float2bfloat16(v);
    g_wqhi[i] = hv;
    g_wqlo[i] = __float2bfloat16(v - __bfloat162float(hv));
}
__global__ void prep_wo(const float* __restrict__ Wo) {
    int i = blockIdx.x * 256 + threadIdx.x;
    if (i >= DD * DD) return;
    int n = i / DD, k = i - (i / DD) * DD;
    float v = Wo[(size_t)k * DD + n];
    __nv_bfloat16 hv = __float2bfloat16(v);
    g_wohi[i] = hv;
    g_wolo[i] = __float2bfloat16(v - __bfloat162float(hv));
}

// ---------------------------------------------------------------------------
// Split-bf16 GEMM with fragment dedup: C = Ahi.Bhi + Ahi.Blo + Alo.Bhi
// CTA tile 256x128, 256 thr (4x2 warps, warp 64x64), 2-stage cp.async.
// grid: (N/128, M/256)
// ---------------------------------------------------------------------------
__global__ __launch_bounds__(256) void gemm_kernel(
    int mode, const float* __restrict__ b0, const float* __restrict__ b1,
    const float* __restrict__ b2, float* __restrict__ out)
{
    extern __shared__ char smem[];
    const uint32_t sbase = smem_u32(smem);
    const int tid  = threadIdx.x;
    const int lane = tid & 31;
    const int warp = tid >> 5;
    const int wm = warp >> 1;        // 0..3
    const int wn = warp & 1;         // 0..1

    const int bn = blockIdx.x, bm = blockIdx.y;

    const char* Ah = (const char*)((mode ? g_ashi : g_xhi) + (size_t)bm * 256 * DD);
    const char* Al = (const char*)((mode ? g_aslo : g_xlo) + (size_t)bm * 256 * DD);
    const char* Bh = (const char*)((mode ? g_wohi : g_wqhi) + (size_t)bn * 128 * DD);
    const char* Bl = (const char*)((mode ? g_wolo : g_wqlo) + (size_t)bn * 128 * DD);

    auto load_stage = [&](int kt, int s) {
        uint32_t sb = sbase + s * STG;
        size_t kb = (size_t)kt * 128;           // byte offset along 1536B rows
        #pragma unroll
        for (int i = 0; i < 8; i++) {           // A: 256 rows x 8 chunks
            int idx = i * 256 + tid;
            int r = idx >> 3, c = idx & 7;
            uint32_t off = SW128(r * 128 + c * 16);
            size_t go = (size_t)r * (DD * 2) + kb + c * 16;
            cp16(sb + S_AHI + off, Ah + go);
            cp16(sb + S_ALO + off, Al + go);
        }
        #pragma unroll
        for (int i = 0; i < 4; i++) {           // B: 128 rows x 8 chunks
            int idx = i * 256 + tid;
            int r = idx >> 3, c = idx & 7;
            uint32_t off = SW128(r * 128 + c * 16);
            size_t go = (size_t)r * (DD * 2) + kb + c * 16;
            cp16(sb + S_BHI + off, Bh + go);
            cp16(sb + S_BLO + off, Bl + go);
        }
        cp_commit();
    };

    float acc[4][8][4];
    #pragma unroll
    for (int mi = 0; mi < 4; mi++)
        #pragma unroll
        for (int ni = 0; ni < 8; ni++)
            #pragma unroll
            for (int j = 0; j < 4; j++) acc[mi][ni][j] = 0.f;

    load_stage(0, 0);

    const int a_row = wm * 64 + (lane & 15);
    const int a_chb = (lane >> 4) * 16;
    const int b_row = wn * 64 + (lane & 7) + ((lane >> 3) & 1) * 8;
    const int b_chb = (lane >> 4) * 16;

    for (int kt = 0; kt < NKC; kt++) {
        if (kt + 1 < NKC) {
            load_stage(kt + 1, (kt + 1) & 1);
            cp_wait<1>();
        } else {
            cp_wait<0>();
        }
        __syncthreads();

        uint32_t sb = sbase + (kt & 1) * STG;

        #pragma unroll
        for (int ks = 0; ks < 4; ks++) {
            uint32_t ahi[4][4], alo[4][4], bhi[8][2], blo[8][2];
            // load A-hi, B-hi
            #pragma unroll
            for (int mi = 0; mi < 4; mi++)
                ldsm4(ahi[mi][0], ahi[mi][1], ahi[mi][2], ahi[mi][3],
                      sb + S_AHI + SW128((a_row + mi * 16) * 128 + ks * 32 + a_chb));
            #pragma unroll
            for (int p = 0; p < 4; p++) {
                uint32_t r0, r1, r2, r3;
                ldsm4(r0, r1, r2, r3,
                      sb + S_BHI + SW128((b_row + p * 16) * 128 + ks * 32 + b_chb));
                bhi[2*p][0] = r0; bhi[2*p][1] = r2;
                bhi[2*p+1][0] = r1; bhi[2*p+1][1] = r3;
            }
            // term 1: ahi . bhi
            #pragma unroll
            for (int mi = 0; mi < 4; mi++)
                #pragma unroll
                for (int ni = 0; ni < 8; ni++)
                    mma16816(acc[mi][ni][0], acc[mi][ni][1], acc[mi][ni][2], acc[mi][ni][3],
                             ahi[mi][0], ahi[mi][1], ahi[mi][2], ahi[mi][3],
                             bhi[ni][0], bhi[ni][1]);
            // load B-lo, term 2: ahi . blo
            #pragma unroll
            for (int p = 0; p < 4; p++) {
                uint32_t r0, r1, r2, r3;
                ldsm4(r0, r1, r2, r3,
                      sb + S_BLO + SW128((b_row + p * 16) * 128 + ks * 32 + b_chb));
                blo[2*p][0] = r0; blo[2*p][1] = r2;
                blo[2*p+1][0] = r1; blo[2*p+1][1] = r3;
            }
            #pragma unroll
            for (int mi = 0; mi < 4; mi++)
                #pragma unroll
                for (int ni = 0; ni < 8; ni++)
                    mma16816(acc[mi][ni][0], acc[mi][ni][1], acc[mi][ni][2], acc[mi][ni][3],
                             ahi[mi][0], ahi[mi][1], ahi[mi][2], ahi[mi][3],
                             blo[ni][0], blo[ni][1]);
            // load A-lo, term 3: alo . bhi
            #pragma unroll
            for (int mi = 0; mi < 4; mi++)
                ldsm4(alo[mi][0], alo[mi][1], alo[mi][2], alo[mi][3],
                      sb + S_ALO + SW128((a_row + mi * 16) * 128 + ks * 32 + a_chb));
            #pragma unroll
            for (int mi = 0; mi < 4; mi++)
                #pragma unroll
                for (int ni = 0; ni < 8; ni++)
                    mma16816(acc[mi][ni][0], acc[mi][ni][1], acc[mi][ni][2], acc[mi][ni][3],
                             alo[mi][0], alo[mi][1], alo[mi][2], alo[mi][3],
                             bhi[ni][0], bhi[ni][1]);
        }
        __syncthreads();
    }

    const int gid = lane >> 2;
    const int tg  = lane & 3;
    #pragma unroll
    for (int mi = 0; mi < 4; mi++) {
        #pragma unroll
        for (int half = 0; half < 2; half++) {
            int m = bm * 256 + wm * 64 + mi * 16 + gid + half * 8;
            #pragma unroll
            for (int ni = 0; ni < 8; ni++) {
                int n = bn * 128 + wn * 64 + ni * 8 + tg * 2;
                float v0 = acc[mi][ni][half * 2 + 0];
                float v1 = acc[mi][ni][half * 2 + 1];
                if (mode == 0) {
                    int which = n / DD;
                    int rem = n - which * DD;
                    int h = rem >> 6, e = rem & 63;
                    const float* bp = ((which == 0) ? b0 : (which == 1) ? b1 : b2) + h * EE + e;
                    v0 += bp[0]; v1 += bp[1];
                    uint32_t hi = pack_hi(v0, v1);
                    uint32_t lo = pack_rn(v0 - trunc_bf(v0), v1 - trunc_bf(v1));
                    __nv_bfloat16* ah = (which == 0) ? g_qhi : (which == 1) ? g_khi : g_vhi;
                    __nv_bfloat16* al = (which == 0) ? g_qlo : (which == 1) ? g_klo : g_vlo;
                    size_t off = (((size_t)(m >> 9) * HH + h) * SS + (m & 511)) * EE + e;
                    *(uint32_t*)(ah + off) = hi;
                    *(uint32_t*)(al + off) = lo;
                } else {
                    float2 w; w.x = v0 + b0[n]; w.y = v1 + b0[n + 1];
                    *(float2*)(out + (size_t)m * DD + n) = w;
                }
            }
        }
    }
}

// ---------------------------------------------------------------------------
// Tensor-core flash attention, split-bf16 (3-term) QK^T and PV.
// grid (S/128, H, B); 256 threads = 8 warps; warp owns 16 q rows.
// smem: QH 0, QL 16K | stage s at 32K+s*32K: KH+0, KL+8K, VH+16K, VL+24K
// ---------------------------------------------------------------------------
#define AT_SMEM (32768 + 2*32768)

__global__ __launch_bounds__(256) void attn_kernel()
{
    extern __shared__ char smem[];
    const uint32_t sb = smem_u32(smem);
    const int tid  = threadIdx.x;
    const int lane = tid & 31;
    const int w    = tid >> 5;

    const int qt = blockIdx.x, h = blockIdx.y, b = blockIdx.z;
    const size_t bh = (size_t)b * HH + h;

    const char* qh_g = (const char*)(g_qhi + (bh * SS + qt * 128) * EE);
    const char* ql_g = (const char*)(g_qlo + (bh * SS + qt * 128) * EE);
    const char* kh_g = (const char*)(g_khi + bh * SS * EE);
    const char* kl_g = (const char*)(g_klo + bh * SS * EE);
    const char* vh_g = (const char*)(g_vhi + bh * SS * EE);
    const char* vl_g = (const char*)(g_vlo + bh * SS * EE);

    #pragma unroll
    for (int i = 0; i < 4; i++) {
        int idx = i * 256 + tid;
        int r = idx >> 3, c = idx & 7;
        cp16(sb + SW128(r * 128 + c * 16), qh_g + (size_t)r * 128 + c * 16);
        cp16(sb + 16384 + SW128(r * 128 + c * 16), ql_g + (size_t)r * 128 + c * 16);
    }

    auto load_kv = [&](int t, int s) {
        uint32_t kb = sb + 32768 + s * 32768;
        size_t rowbase = (size_t)t * 64 * 128;
        #pragma unroll
        for (int i = 0; i < 8; i++) {
            int tile = i >> 1;
            int r = (i & 1) * 32 + (tid >> 3);
            int c = tid & 7;
            const char* src = (tile == 0) ? kh_g : (tile == 1) ? kl_g
                            : (tile == 2) ? vh_g : vl_g;
            cp16(kb + tile * 8192 + SW128(r * 128 + c * 16),
                 src + rowbase + (size_t)r * 128 + c * 16);
        }
    };

    load_kv(0, 0);
    cp_commit();

    float oacc[8][4];
    #pragma unroll
    for (int ni = 0; ni < 8; ni++)
        #pragma unroll
        for (int j = 0; j < 4; j++) oacc[ni][j] = 0.f;
    float m0 = -1e30f, m1 = -1e30f, l0 = 0.f, l1 = 0.f;

    uint32_t qh[4][4], ql[4][4];

    const int krow = (lane & 7) + ((lane >> 3) & 1) * 8;
    const int kch  = (lane >> 4) * 16;

    for (int t = 0; t < 8; t++) {
        cp_wait<0>();
        __syncthreads();

        if (t == 0) {
            #pragma unroll
            for (int ks = 0; ks < 4; ks++) {
                uint32_t ad = SW128((w * 16 + (lane & 15)) * 128 + ks * 32 + (lane >> 4) * 16);
                ldsm4(qh[ks][0], qh[ks][1], qh[ks][2], qh[ks][3], sb + ad);
                ldsm4(ql[ks][0], ql[ks][1], ql[ks][2], ql[ks][3], sb + 16384 + ad);
            }
        }

        if (t < 7) { load_kv(t + 1, (t + 1) & 1); cp_commit(); }
        else       { cp_commit(); }

        uint32_t kb = sb + 32768 + (t & 1) * 32768;

        float sacc[8][4];
        #pragma unroll
        for (int ni = 0; ni < 8; ni++)
            #pragma unroll
            for (int j = 0; j < 4; j++) sacc[ni][j] = 0.f;

        #pragma unroll
        for (int ks = 0; ks < 4; ks++) {
            #pragma unroll
            for (int nj = 0; nj < 4; nj++) {
                uint32_t ad = SW128((nj * 16 + krow) * 128 + ks * 32 + kch);
                uint32_t h0, h1, h2, h3, e0, e1, e2, e3;
                ldsm4(h0, h1, h2, h3, kb + ad);
                ldsm4(e0, e1, e2, e3, kb + 8192 + ad);
                mma16816(sacc[2*nj][0], sacc[2*nj][1], sacc[2*nj][2], sacc[2*nj][3],
                         qh[ks][0], qh[ks][1], qh[ks][2], qh[ks][3], h0, h2);
                mma16816(sacc[2*nj+1][0], sacc[2*nj+1][1], sacc[2*nj+1][2], sacc[2*nj+1][3],
                         qh[ks][0], qh[ks][1], qh[ks][2], qh[ks][3], h1, h3);
                mma16816(sacc[2*nj][0], sacc[2*nj][1], sacc[2*nj][2], sacc[2*nj][3],
                         qh[ks][0], qh[ks][1], qh[ks][2], qh[ks][3], e0, e2);
                mma16816(sacc[2*nj+1][0], sacc[2*nj+1][1], sacc[2*nj+1][2], sacc[2*nj+1][3],
                         qh[ks][0], qh[ks][1], qh[ks][2], qh[ks][3], e1, e3);
                mma16816(sacc[2*nj][0], sacc[2*nj][1], sacc[2*nj][2], sacc[2*nj][3],
                         ql[ks][0], ql[ks][1], ql[ks][2], ql[ks][3], h0, h2);
                mma16816(sacc[2*nj+1][0], sacc[2*nj+1][1], sacc[2*nj+1][2], sacc[2*nj+1][3],
                         ql[ks][0], ql[ks][1], ql[ks][2], ql[ks][3], h1, h3);
            }
        }

        float ml0 = -1e30f, ml1 = -1e30f;
        #pragma unroll
        for (int ni = 0; ni < 8; ni++) {
            sacc[ni][0] *= 0.125f; sacc[ni][1] *= 0.125f;
            sacc[ni][2] *= 0.125f; sacc[ni][3] *= 0.125f;
            ml0 = fmaxf(ml0, fmaxf(sacc[ni][0], sacc[ni][1]));
            ml1 = fmaxf(ml1, fmaxf(sacc[ni][2], sacc[ni][3]));
        }
        ml0 = fmaxf(ml0, __shfl_xor_sync(0xffffffffu, ml0, 1));
        ml0 = fmaxf(ml0, __shfl_xor_sync(0xffffffffu, ml0, 2));
        ml1 = fmaxf(ml1, __shfl_xor_sync(0xffffffffu, ml1, 1));
        ml1 = fmaxf(ml1, __shfl_xor_sync(0xffffffffu, ml1, 2));

        float mn0 = fmaxf(m0, ml0), mn1 = fmaxf(m1, ml1);
        float corr0 = __expf(m0 - mn0), corr1 = __expf(m1 - mn1);
        m0 = mn0; m1 = mn1;

        float rs0 = 0.f, rs1 = 0.f;
        #pragma unroll
        for (int ni = 0; ni < 8; ni++) {
            sacc[ni][0] = __expf(sacc[ni][0] - mn0);
            sacc[ni][1] = __expf(sacc[ni][1] - mn0);
            sacc[ni][2] = __expf(sacc[ni][2] - mn1);
            sacc[ni][3] = __expf(sacc[ni][3] - mn1);
            rs0 += sacc[ni][0] + sacc[ni][1];
            rs1 += sacc[ni][2] + sacc[ni][3];
        }
        rs0 += __shfl_xor_sync(0xffffffffu, rs0, 1);
        rs0 += __shfl_xor_sync(0xffffffffu, rs0, 2);
        rs1 += __shfl_xor_sync(0xffffffffu, rs1, 1);
        rs1 += __shfl_xor_sync(0xffffffffu, rs1, 2);
        l0 = l0 * corr0 + rs0;
        l1 = l1 * corr1 + rs1;
        #pragma unroll
        for (int ni = 0; ni < 8; ni++) {
            oacc[ni][0] *= corr0; oacc[ni][1] *= corr0;
            oacc[ni][2] *= corr1; oacc[ni][3] *= corr1;
        }

        #pragma unroll
        for (int ks = 0; ks < 4; ks++) {
            float* p0 = sacc[2 * ks];
            float* p1 = sacc[2 * ks + 1];
            uint32_t ah0 = pack_hi(p0[0], p0[1]);
            uint32_t ah1 = pack_hi(p0[2], p0[3]);
            uint32_t ah2 = pack_hi(p1[0], p1[1]);
            uint32_t ah3 = pack_hi(p1[2], p1[3]);
            uint32_t al0 = pack_rn(p0[0] - trunc_bf(p0[0]), p0[1] - trunc_bf(p0[1]));
            uint32_t al1 = pack_rn(p0[2] - trunc_bf(p0[2]), p0[3] - trunc_bf(p0[3]));
            uint32_t al2 = pack_rn(p1[0] - trunc_bf(p1[0]), p1[1] - trunc_bf(p1[1]));
            uint32_t al3 = pack_rn(p1[2] - trunc_bf(p1[2]), p1[3] - trunc_bf(p1[3]));
            #pragma unroll
            for (int ep = 0; ep < 4; ep++) {
                uint32_t ad = SW128((ks * 16 + krow) * 128 + ep * 32 + kch);
                uint32_t vh0, vh1, vh2, vh3, vl0_, vl1_, vl2_, vl3_;
                ldsm4t(vh0, vh1, vh2, vh3, kb + 16384 + ad);
                ldsm4t(vl0_, vl1_, vl2_, vl3_, kb + 24576 + ad);
                mma16816(oacc[2*ep][0], oacc[2*ep][1], oacc[2*ep][2], oacc[2*ep][3],
                         ah0, ah1, ah2, ah3, vh0, vh1);
                mma16816(oacc[2*ep+1][0], oacc[2*ep+1][1], oacc[2*ep+1][2], oacc[2*ep+1][3],
                         ah0, ah1, ah2, ah3, vh2, vh3);
                mma16816(oacc[2*ep][0], oacc[2*ep][1], oacc[2*ep][2], oacc[2*ep][3],
                         ah0, ah1, ah2, ah3, vl0_, vl1_);
                mma16816(oacc[2*ep+1][0], oacc[2*ep+1][1], oacc[2*ep+1][2], oacc[2*ep+1][3],
                         ah0, ah1, ah2, ah3, vl2_, vl3_);
                mma16816(oacc[2*ep][0], oacc[2*ep][1], oacc[2*ep][2], oacc[2*ep][3],
                         al0, al1, al2, al3, vh0, vh1);
                mma16816(oacc[2*ep+1][0], oacc[2*ep+1][1], oacc[2*ep+1][2], oacc[2*ep+1][3],
                         al0, al1, al2, al3, vh2, vh3);
            }
        }
    }

    // epilogue: normalize + write hi/lo rows
    float inv0 = 1.f / l0, inv1 = 1.f / l1;
    int mrow = b * SS + qt * 128 + w * 16 + (lane >> 2);
    int colb = h * 64 + (lane & 3) * 2;
    #pragma unroll
    for (int ni = 0; ni < 8; ni++) {
        float v0 = oacc[ni][0] * inv0, v1 = oacc[ni][1] * inv0;
        float v2 = oacc[ni][2] * inv1, v3 = oacc[ni][3] * inv1;
        size_t base0 = (size_t)mrow * DD + colb + ni * 8;
        size_t base1 = (size_t)(mrow + 8) * DD + colb + ni * 8;
        *(uint32_t*)(g_ashi + base0) = pack_hi(v0, v1);
        *(uint32_t*)(g_aslo + base0) = pack_rn(v0 - trunc_bf(v0), v1 - trunc_bf(v1));
        *(uint32_t*)(g_ashi + base1) = pack_hi(v2, v3);
        *(uint32_t*)(g_aslo + base1) = pack_rn(v2 - trunc_bf(v2), v3 - trunc_bf(v3));
    }
}

// ---------------------------------------------------------------------------
extern "C" void kernel_launch(void* const* d_in, const int* in_sizes, int n_in,
                              void* d_out, int out_size)
{
    const float* x  = (const float*)d_in[0];
    const float* Wq = (const float*)d_in[1];
    const float* Wk = (const float*)d_in[2];
    const float* Wv = (const float*)d_in[3];
    const float* bq = (const float*)d_in[4];
    const float* bk = (const float*)d_in[5];
    const float* bv = (const float*)d_in[6];
    const float* Wo = (const float*)d_in[7];
    const float* bo = (const float*)d_in[8];
    float* out = (float*)d_out;

    cudaFuncSetAttribute(gemm_kernel, cudaFuncAttributeMaxDynamicSharedMemorySize, G_SMEM);
    cudaFuncSetAttribute(attn_kernel, cudaFuncAttributeMaxDynamicSharedMemorySize, AT_SMEM);

    prep_x<<<(M_TOT * DD + 255) / 256, 256>>>(x);
    prep_wqkv<<<(N_QKV * DD + 255) / 256, 256>>>(Wq, Wk, Wv);
    prep_wo<<<(DD * DD + 255) / 256, 256>>>(Wo);

    gemm_kernel<<<dim3(N_QKV / 128, M_TOT / 256), 256, G_SMEM>>>(
        0, bq, bk, bv, nullptr);

    attn_kernel<<<dim3(SS / 128, HH, BB), 256, AT_SMEM>>>();

    gemm_kernel<<<dim3(DD / 128, M_TOT / 256), 256, G_SMEM>>>(
        1, bo, bo, bo, out);
}

// round 12
// speedup vs baseline: 3.1170x; 1.0720x over previous
#include <cuda_runtime.h>
#include <cuda_bf16.h>
#include <math.h>
#include <stdint.h>

#define BB 32
#define SS 512
#define DD 768
#define HH 12
#define EE 64

#define M_TOT (BB*SS)        // 16384
#define N_QKV (3*DD)         // 2304
#define NKC   (DD/64)        // 12 base-k chunks of 64 (bf16 GEMM)
#define NKCI  (DD/128)       // 6 k-chunks of 128 (int8 GEMM)

// bf16 GEMM tiling: 256x128 CTA tile, 8 warps (4x2), warp tile 64x64, 2-stage
#define S_AHI 0
#define S_ALO 32768
#define S_BHI 65536
#define S_BLO 81920
#define STG   98304          // 96KB per stage
#define G_SMEM (2*STG)       // 192KB

// int8 proj GEMM smem per stage: A1 16K | A2 16K | B1 8K | B2 8K = 48KB, 2 stages
#define I_A1 0
#define I_A2 16384
#define I_B1 32768
#define I_B2 40960
#define ISTG 49152
#define I_SMEM (2*ISTG)      // 96KB

// ---------------- device scratch ----------------
__device__ __nv_bfloat16 g_xhi[M_TOT*DD],  g_xlo[M_TOT*DD];    // x split
__device__ __nv_bfloat16 g_ashi[M_TOT*DD], g_aslo[M_TOT*DD];   // attn out split
__device__ __nv_bfloat16 g_wqhi[N_QKV*DD], g_wqlo[N_QKV*DD];   // qkv W^T split
__device__ __nv_bfloat16 g_qhi[BB*HH*SS*EE], g_qlo[BB*HH*SS*EE];
__device__ __nv_bfloat16 g_khi[BB*HH*SS*EE], g_klo[BB*HH*SS*EE];
__device__ __nv_bfloat16 g_vhi[BB*HH*SS*EE], g_vlo[BB*HH*SS*EE];
// int8 proj path
__device__ int8_t g_a1[M_TOT*DD], g_a2[M_TOT*DD];
__device__ float  g_sa[M_TOT];
__device__ int8_t g_wo1[DD*DD],   g_wo2[DD*DD];
__device__ float  g_swo[DD];

// ---------------- helpers ----------------
#define SW128(o) ((o) ^ (((o) >> 3) & 0x70))

__device__ __forceinline__ uint32_t smem_u32(const void* p) {
    return (uint32_t)__cvta_generic_to_shared(p);
}
__device__ __forceinline__ void cp16(uint32_t dst, const void* src) {
    asm volatile("cp.async.cg.shared.global [%0], [%1], 16;" :: "r"(dst), "l"(src) : "memory");
}
__device__ __forceinline__ void cp_commit() {
    asm volatile("cp.async.commit_group;" ::: "memory");
}
template <int N> __device__ __forceinline__ void cp_wait() {
    asm volatile("cp.async.wait_group %0;" :: "n"(N) : "memory");
}
__device__ __forceinline__ void ldsm4(uint32_t& a, uint32_t& b, uint32_t& c, uint32_t& d,
                                      uint32_t addr) {
    asm volatile("ldmatrix.sync.aligned.m8n8.x4.shared.b16 {%0,%1,%2,%3}, [%4];"
                 : "=r"(a), "=r"(b), "=r"(c), "=r"(d) : "r"(addr));
}
__device__ __forceinline__ void ldsm4t(uint32_t& a, uint32_t& b, uint32_t& c, uint32_t& d,
                                       uint32_t addr) {
    asm volatile("ldmatrix.sync.aligned.m8n8.x4.trans.shared.b16 {%0,%1,%2,%3}, [%4];"
                 : "=r"(a), "=r"(b), "=r"(c), "=r"(d) : "r"(addr));
}
__device__ __forceinline__ void mma16816(float& c0, float& c1, float& c2, float& c3,
                                         uint32_t a0, uint32_t a1, uint32_t a2, uint32_t a3,
                                         uint32_t b0, uint32_t b1) {
    asm volatile(
        "mma.sync.aligned.m16n8k16.row.col.f32.bf16.bf16.f32 "
        "{%0,%1,%2,%3}, {%4,%5,%6,%7}, {%8,%9}, {%0,%1,%2,%3};"
        : "+f"(c0), "+f"(c1), "+f"(c2), "+f"(c3)
        : "r"(a0), "r"(a1), "r"(a2), "r"(a3), "r"(b0), "r"(b1));
}
__device__ __forceinline__ void imma16832(int& c0, int& c1, int& c2, int& c3,
                                          uint32_t a0, uint32_t a1, uint32_t a2, uint32_t a3,
                                          uint32_t b0, uint32_t b1) {
    asm volatile(
        "mma.sync.aligned.m16n8k32.row.col.s32.s8.s8.s32 "
        "{%0,%1,%2,%3}, {%4,%5,%6,%7}, {%8,%9}, {%0,%1,%2,%3};"
        : "+r"(c0), "+r"(c1), "+r"(c2), "+r"(c3)
        : "r"(a0), "r"(a1), "r"(a2), "r"(a3), "r"(b0), "r"(b1));
}
__device__ __forceinline__ uint32_t pack_hi(float v0, float v1) {
    return __byte_perm(__float_as_uint(v0), __float_as_uint(v1), 0x7632);
}
__device__ __forceinline__ float trunc_bf(float v) {
    return __uint_as_float(__float_as_uint(v) & 0xffff0000u);
}
__device__ __forceinline__ uint32_t pack_rn(float l0, float l1) {
    uint32_t r;
    asm("cvt.rn.bf16x2.f32 %0, %1, %2;" : "=r"(r) : "f"(l1), "f"(l0));
    return r;
}

// ---------------------------------------------------------------------------
// prep kernels (round-7 verbatim): fp32 -> separate hi/lo bf16 arrays
// ---------------------------------------------------------------------------
__global__ void prep_x(const float* __restrict__ x) {
    int i = blockIdx.x * 256 + threadIdx.x;
    if (i >= M_TOT * DD) return;
    float v = x[i];
    __nv_bfloat16 h = __float2bfloat16(v);
    g_xhi[i] = h;
    g_xlo[i] = __float2bfloat16(v - __bfloat162float(h));
}
__global__ void prep_wqkv(const float* __restrict__ Wq, const float* __restrict__ Wk,
                          const float* __restrict__ Wv) {
    int i = blockIdx.x * 256 + threadIdx.x;
    if (i >= N_QKV * DD) return;
    int n = i / DD, k = i - (i / DD) * DD;
    int which = n / DD;
    int rem = n - which * DD;
    int h = rem >> 6, e = rem & 63;
    const float* W = (which == 0) ? Wq : (which == 1) ? Wk : Wv;
    float v = W[((size_t)h * DD + k) * EE + e];
    __nv_bfloat16 hv = __float2bfloat16(v);
    g_wqhi[i] = hv;
    g_wqlo[i] = __float2bfloat16(v - __bfloat162float(hv));
}

// ---------------------------------------------------------------------------
// conservative quant kernels: one block per row, plain loops, smem reduction
// v ~= s * (128*a1 + a2)
// ---------------------------------------------------------------------------
__global__ __launch_bounds__(256) void quant_att() {
    int row = blockIdx.x;
    __shared__ float red[256];
    float m = 0.f;
    for (int j = threadIdx.x; j < DD; j += 256) {
        float v = __bfloat162float(g_ashi[(size_t)row * DD + j])
                + __bfloat162float(g_aslo[(size_t)row * DD + j]);
        m = fmaxf(m, fabsf(v));
    }
    red[threadIdx.x] = m;
    __syncthreads();
    for (int s = 128; s > 0; s >>= 1) {
        if (threadIdx.x < s)
            red[threadIdx.x] = fmaxf(red[threadIdx.x], red[threadIdx.x + s]);
        __syncthreads();
    }
    float mx = red[0];
    float inv = mx > 0.f ? 16256.f / mx : 0.f;
    if (threadIdx.x == 0) g_sa[row] = mx > 0.f ? mx / 16256.f : 0.f;
    for (int j = threadIdx.x; j < DD; j += 256) {
        float v = __bfloat162float(g_ashi[(size_t)row * DD + j])
                + __bfloat162float(g_aslo[(size_t)row * DD + j]);
        float ai = rintf(v * inv);
        int a1 = (int)rintf(ai * 0.0078125f);
        int a2 = (int)ai - 128 * a1;
        g_a1[(size_t)row * DD + j] = (int8_t)a1;
        g_a2[(size_t)row * DD + j] = (int8_t)a2;
    }
}

__global__ __launch_bounds__(256) void quant_wo(const float* __restrict__ Wo) {
    int row = blockIdx.x;          // output column n
    __shared__ float red[256];
    float m = 0.f;
    for (int j = threadIdx.x; j < DD; j += 256)
        m = fmaxf(m, fabsf(Wo[(size_t)j * DD + row]));
    red[threadIdx.x] = m;
    __syncthreads();
    for (int s = 128; s > 0; s >>= 1) {
        if (threadIdx.x < s)
            red[threadIdx.x] = fmaxf(red[threadIdx.x], red[threadIdx.x + s]);
        __syncthreads();
    }
    float mx = red[0];
    float inv = mx > 0.f ? 16256.f / mx : 0.f;
    if (threadIdx.x == 0) g_swo[row] = mx > 0.f ? mx / 16256.f : 0.f;
    for (int j = threadIdx.x; j < DD; j += 256) {
        float v = Wo[(size_t)j * DD + row];
        float ai = rintf(v * inv);
        int a1 = (int)rintf(ai * 0.0078125f);
        int a2 = (int)ai - 128 * a1;
        g_wo1[(size_t)row * DD + j] = (int8_t)a1;
        g_wo2[(size_t)row * DD + j] = (int8_t)a2;
    }
}

// ---------------------------------------------------------------------------
// bf16 split GEMM (round-7 verbatim, qkv only):
// C = Ahi.Bhi + Ahi.Blo + Alo.Bhi ; CTA 256x128, warp 64x64, 2-stage
// ---------------------------------------------------------------------------
__global__ __launch_bounds__(256) void gemm_kernel(
    const float* __restrict__ b0, const float* __restrict__ b1,
    const float* __restrict__ b2)
{
    extern __shared__ char smem[];
    const uint32_t sbase = smem_u32(smem);
    const int tid  = threadIdx.x;
    const int lane = tid & 31;
    const int warp = tid >> 5;
    const int wm = warp >> 1;
    const int wn = warp & 1;

    const int bn = blockIdx.x, bm = blockIdx.y;

    const char* Ah = (const char*)(g_xhi + (size_t)bm * 256 * DD);
    const char* Al = (const char*)(g_xlo + (size_t)bm * 256 * DD);
    const char* Bh = (const char*)(g_wqhi + (size_t)bn * 128 * DD);
    const char* Bl = (const char*)(g_wqlo + (size_t)bn * 128 * DD);

    auto load_stage = [&](int kt, int s) {
        uint32_t sb = sbase + s * STG;
        size_t kb = (size_t)kt * 128;
        #pragma unroll
        for (int i = 0; i < 8; i++) {
            int idx = i * 256 + tid;
            int r = idx >> 3, c = idx & 7;
            uint32_t off = SW128(r * 128 + c * 16);
            size_t go = (size_t)r * (DD * 2) + kb + c * 16;
            cp16(sb + S_AHI + off, Ah + go);
            cp16(sb + S_ALO + off, Al + go);
        }
        #pragma unroll
        for (int i = 0; i < 4; i++) {
            int idx = i * 256 + tid;
            int r = idx >> 3, c = idx & 7;
            uint32_t off = SW128(r * 128 + c * 16);
            size_t go = (size_t)r * (DD * 2) + kb + c * 16;
            cp16(sb + S_BHI + off, Bh + go);
            cp16(sb + S_BLO + off, Bl + go);
        }
        cp_commit();
    };

    float acc[4][8][4];
    #pragma unroll
    for (int mi = 0; mi < 4; mi++)
        #pragma unroll
        for (int ni = 0; ni < 8; ni++)
            #pragma unroll
            for (int j = 0; j < 4; j++) acc[mi][ni][j] = 0.f;

    load_stage(0, 0);

    const int a_row = wm * 64 + (lane & 15);
    const int a_chb = (lane >> 4) * 16;
    const int b_row = wn * 64 + (lane & 7) + ((lane >> 3) & 1) * 8;
    const int b_chb = (lane >> 4) * 16;

    for (int kt = 0; kt < NKC; kt++) {
        if (kt + 1 < NKC) {
            load_stage(kt + 1, (kt + 1) & 1);
            cp_wait<1>();
        } else {
            cp_wait<0>();
        }
        __syncthreads();

        uint32_t sb = sbase + (kt & 1) * STG;

        #pragma unroll
        for (int ks = 0; ks < 4; ks++) {
            uint32_t ahi[4][4], alo[4][4], bhi[8][2], blo[8][2];
            #pragma unroll
            for (int mi = 0; mi < 4; mi++)
                ldsm4(ahi[mi][0], ahi[mi][1], ahi[mi][2], ahi[mi][3],
                      sb + S_AHI + SW128((a_row + mi * 16) * 128 + ks * 32 + a_chb));
            #pragma unroll
            for (int p = 0; p < 4; p++) {
                uint32_t r0, r1, r2, r3;
                ldsm4(r0, r1, r2, r3,
                      sb + S_BHI + SW128((b_row + p * 16) * 128 + ks * 32 + b_chb));
                bhi[2*p][0] = r0; bhi[2*p][1] = r2;
                bhi[2*p+1][0] = r1; bhi[2*p+1][1] = r3;
            }
            #pragma unroll
            for (int mi = 0; mi < 4; mi++)
                #pragma unroll
                for (int ni = 0; ni < 8; ni++)
                    mma16816(acc[mi][ni][0], acc[mi][ni][1], acc[mi][ni][2], acc[mi][ni][3],
                             ahi[mi][0], ahi[mi][1], ahi[mi][2], ahi[mi][3],
                             bhi[ni][0], bhi[ni][1]);
            #pragma unroll
            for (int p = 0; p < 4; p++) {
                uint32_t r0, r1, r2, r3;
                ldsm4(r0, r1, r2, r3,
                      sb + S_BLO + SW128((b_row + p * 16) * 128 + ks * 32 + b_chb));
                blo[2*p][0] = r0; blo[2*p][1] = r2;
                blo[2*p+1][0] = r1; blo[2*p+1][1] = r3;
            }
            #pragma unroll
            for (int mi = 0; mi < 4; mi++)
                #pragma unroll
                for (int ni = 0; ni < 8; ni++)
                    mma16816(acc[mi][ni][0], acc[mi][ni][1], acc[mi][ni][2], acc[mi][ni][3],
                             ahi[mi][0], ahi[mi][1], ahi[mi][2], ahi[mi][3],
                             blo[ni][0], blo[ni][1]);
            #pragma unroll
            for (int mi = 0; mi < 4; mi++)
                ldsm4(alo[mi][0], alo[mi][1], alo[mi][2], alo[mi][3],
                      sb + S_ALO + SW128((a_row + mi * 16) * 128 + ks * 32 + a_chb));
            #pragma unroll
            for (int mi = 0; mi < 4; mi++)
                #pragma unroll
                for (int ni = 0; ni < 8; ni++)
                    mma16816(acc[mi][ni][0], acc[mi][ni][1], acc[mi][ni][2], acc[mi][ni][3],
                             alo[mi][0], alo[mi][1], alo[mi][2], alo[mi][3],
                             bhi[ni][0], bhi[ni][1]);
        }
        __syncthreads();
    }

    const int gid = lane >> 2;
    const int tg  = lane & 3;
    #pragma unroll
    for (int mi = 0; mi < 4; mi++) {
        #pragma unroll
        for (int half = 0; half < 2; half++) {
            int m = bm * 256 + wm * 64 + mi * 16 + gid + half * 8;
            #pragma unroll
            for (int ni = 0; ni < 8; ni++) {
                int n = bn * 128 + wn * 64 + ni * 8 + tg * 2;
                float v0 = acc[mi][ni][half * 2 + 0];
                float v1 = acc[mi][ni][half * 2 + 1];
                int which = n / DD;
                int rem = n - which * DD;
                int h = rem >> 6, e = rem & 63;
                const float* bp = ((which == 0) ? b0 : (which == 1) ? b1 : b2) + h * EE + e;
                v0 += bp[0]; v1 += bp[1];
                uint32_t hi = pack_hi(v0, v1);
                uint32_t lo = pack_rn(v0 - trunc_bf(v0), v1 - trunc_bf(v1));
                __nv_bfloat16* ah = (which == 0) ? g_qhi : (which == 1) ? g_khi : g_vhi;
                __nv_bfloat16* al = (which == 0) ? g_qlo : (which == 1) ? g_klo : g_vlo;
                size_t off = (((size_t)(m >> 9) * HH + h) * SS + (m & 511)) * EE + e;
                *(uint32_t*)(ah + off) = hi;
                *(uint32_t*)(al + off) = lo;
            }
        }
    }
}

// ---------------------------------------------------------------------------
// int8 proj GEMM: out = sA*sWo*(16384*A1B1 + 128*(A1B2 + A2B1)) + bo
// CTA 128x64, 8 warps (4x2), warp tile 32x32, 2-stage, k-chunk 128
// ---------------------------------------------------------------------------
__global__ __launch_bounds__(256) void gemm_proj_i8(
    const float* __restrict__ bo, float* __restrict__ out)
{
    extern __shared__ char smem[];
    const uint32_t sbase = smem_u32(smem);
    const int tid  = threadIdx.x;
    const int lane = tid & 31;
    const int warp = tid >> 5;
    const int wm = warp >> 1;        // 0..3
    const int wn = warp & 1;         // 0..1

    const int bn = blockIdx.x, bm = blockIdx.y;

    const char* A1p = (const char*)(g_a1 + (size_t)bm * 128 * DD);
    const char* A2p = (const char*)(g_a2 + (size_t)bm * 128 * DD);
    const char* B1p = (const char*)(g_wo1 + (size_t)bn * 64 * DD);
    const char* B2p = (const char*)(g_wo2 + (size_t)bn * 64 * DD);

    auto load_stage = [&](int kt, int s) {
        uint32_t sb = sbase + s * ISTG;
        size_t kb = (size_t)kt * 128;
        #pragma unroll
        for (int i = 0; i < 4; i++) {
            int idx = i * 256 + tid;
            int r = idx >> 3, c = idx & 7;
            uint32_t off = SW128(r * 128 + c * 16);
            size_t go = (size_t)r * DD + kb + c * 16;
            cp16(sb + I_A1 + off, A1p + go);
            cp16(sb + I_A2 + off, A2p + go);
        }
        #pragma unroll
        for (int i = 0; i < 2; i++) {
            int idx = i * 256 + tid;
            int r = idx >> 3, c = idx & 7;
            uint32_t off = SW128(r * 128 + c * 16);
            size_t go = (size_t)r * DD + kb + c * 16;
            cp16(sb + I_B1 + off, B1p + go);
            cp16(sb + I_B2 + off, B2p + go);
        }
        cp_commit();
    };

    int acc1[2][4][4], acc2[2][4][4];
    #pragma unroll
    for (int mi = 0; mi < 2; mi++)
        #pragma unroll
        for (int ni = 0; ni < 4; ni++)
            #pragma unroll
            for (int j = 0; j < 4; j++) { acc1[mi][ni][j] = 0; acc2[mi][ni][j] = 0; }

    load_stage(0, 0);

    const int a_row = wm * 32 + (lane & 15);
    const int a_chb = (lane >> 4) * 16;
    const int b_row = wn * 32 + (lane & 7) + ((lane >> 3) & 1) * 8;
    const int b_chb = (lane >> 4) * 16;

    for (int kt = 0; kt < NKCI; kt++) {
        if (kt + 1 < NKCI) {
            load_stage(kt + 1, (kt + 1) & 1);
            cp_wait<1>();
        } else {
            cp_wait<0>();
        }
        __syncthreads();

        uint32_t sb = sbase + (kt & 1) * ISTG;

        #pragma unroll
        for (int ks = 0; ks < 4; ks++) {
            uint32_t a1f[2][4], a2f[2][4], b1f[4][2], b2f[4][2];
            #pragma unroll
            for (int mi = 0; mi < 2; mi++)
                ldsm4(a1f[mi][0], a1f[mi][1], a1f[mi][2], a1f[mi][3],
                      sb + I_A1 + SW128((a_row + mi * 16) * 128 + ks * 32 + a_chb));
            #pragma unroll
            for (int p = 0; p < 2; p++) {
                uint32_t r0, r1, r2, r3;
                ldsm4(r0, r1, r2, r3,
                      sb + I_B1 + SW128((b_row + p * 16) * 128 + ks * 32 + b_chb));
                b1f[2*p][0] = r0; b1f[2*p][1] = r2;
                b1f[2*p+1][0] = r1; b1f[2*p+1][1] = r3;
            }
            #pragma unroll
            for (int mi = 0; mi < 2; mi++)
                #pragma unroll
                for (int ni = 0; ni < 4; ni++)
                    imma16832(acc1[mi][ni][0], acc1[mi][ni][1], acc1[mi][ni][2], acc1[mi][ni][3],
                              a1f[mi][0], a1f[mi][1], a1f[mi][2], a1f[mi][3],
                              b1f[ni][0], b1f[ni][1]);
            #pragma unroll
            for (int p = 0; p < 2; p++) {
                uint32_t r0, r1, r2, r3;
                ldsm4(r0, r1, r2, r3,
                      sb + I_B2 + SW128((b_row + p * 16) * 128 + ks * 32 + b_chb));
                b2f[2*p][0] = r0; b2f[2*p][1] = r2;
                b2f[2*p+1][0] = r1; b2f[2*p+1][1] = r3;
            }
            #pragma unroll
            for (int mi = 0; mi < 2; mi++)
                #pragma unroll
                for (int ni = 0; ni < 4; ni++)
                    imma16832(acc2[mi][ni][0], acc2[mi][ni][1], acc2[mi][ni][2], acc2[mi][ni][3],
                              a1f[mi][0], a1f[mi][1], a1f[mi][2], a1f[mi][3],
                              b2f[ni][0], b2f[ni][1]);
            #pragma unroll
            for (int mi = 0; mi < 2; mi++)
                ldsm4(a2f[mi][0], a2f[mi][1], a2f[mi][2], a2f[mi][3],
                      sb + I_A2 + SW128((a_row + mi * 16) * 128 + ks * 32 + a_chb));
            #pragma unroll
            for (int mi = 0; mi < 2; mi++)
                #pragma unroll
                for (int ni = 0; ni < 4; ni++)
                    imma16832(acc2[mi][ni][0], acc2[mi][ni][1], acc2[mi][ni][2], acc2[mi][ni][3],
                              a2f[mi][0], a2f[mi][1], a2f[mi][2], a2f[mi][3],
                              b1f[ni][0], b1f[ni][1]);
        }
        __syncthreads();
    }

    const int gid = lane >> 2;
    const int tg  = lane & 3;
    #pragma unroll
    for (int mi = 0; mi < 2; mi++) {
        #pragma unroll
        for (int half = 0; half < 2; half++) {
            int m = bm * 128 + wm * 32 + mi * 16 + gid + half * 8;
            float sam = g_sa[m];
            #pragma unroll
            for (int ni = 0; ni < 4; ni++) {
                int n = bn * 64 + wn * 32 + ni * 8 + tg * 2;
                float v0 = sam * g_swo[n]
                         * (16384.f * (float)acc1[mi][ni][half * 2 + 0]
                          + 128.f   * (float)acc2[mi][ni][half * 2 + 0]);
                float v1 = sam * g_swo[n + 1]
                         * (16384.f * (float)acc1[mi][ni][half * 2 + 1]
                          + 128.f   * (float)acc2[mi][ni][half * 2 + 1]);
                float2 w; w.x = v0 + bo[n]; w.y = v1 + bo[n + 1];
                *(float2*)(out + (size_t)m * DD + n) = w;
            }
        }
    }
}

// ---------------------------------------------------------------------------
// Tensor-core flash attention (round-7 verbatim)
// ---------------------------------------------------------------------------
#define AT_SMEM (32768 + 2*32768)

__global__ __launch_bounds__(256) void attn_kernel()
{
    extern __shared__ char smem[];
    const uint32_t sb = smem_u32(smem);
    const int tid  = threadIdx.x;
    const int lane = tid & 31;
    const int w    = tid >> 5;

    const int qt = blockIdx.x, h = blockIdx.y, b = blockIdx.z;
    const size_t bh = (size_t)b * HH + h;

    const char* qh_g = (const char*)(g_qhi + (bh * SS + qt * 128) * EE);
    const char* ql_g = (const char*)(g_qlo + (bh * SS + qt * 128) * EE);
    const char* kh_g = (const char*)(g_khi + bh * SS * EE);
    const char* kl_g = (const char*)(g_klo + bh * SS * EE);
    const char* vh_g = (const char*)(g_vhi + bh * SS * EE);
    const char* vl_g = (const char*)(g_vlo + bh * SS * EE);

    #pragma unroll
    for (int i = 0; i < 4; i++) {
        int idx = i * 256 + tid;
        int r = idx >> 3, c = idx & 7;
        cp16(sb + SW128(r * 128 + c * 16), qh_g + (size_t)r * 128 + c * 16);
        cp16(sb + 16384 + SW128(r * 128 + c * 16), ql_g + (size_t)r * 128 + c * 16);
    }

    auto load_kv = [&](int t, int s) {
        uint32_t kb = sb + 32768 + s * 32768;
        size_t rowbase = (size_t)t * 64 * 128;
        #pragma unroll
        for (int i = 0; i < 8; i++) {
            int tile = i >> 1;
            int r = (i & 1) * 32 + (tid >> 3);
            int c = tid & 7;
            const char* src = (tile == 0) ? kh_g : (tile == 1) ? kl_g
                            : (tile == 2) ? vh_g : vl_g;
            cp16(kb + tile * 8192 + SW128(r * 128 + c * 16),
                 src + rowbase + (size_t)r * 128 + c * 16);
        }
    };

    load_kv(0, 0);
    cp_commit();

    float oacc[8][4];
    #pragma unroll
    for (int ni = 0; ni < 8; ni++)
        #pragma unroll
        for (int j = 0; j < 4; j++) oacc[ni][j] = 0.f;
    float m0 = -1e30f, m1 = -1e30f, l0 = 0.f, l1 = 0.f;

    uint32_t qh[4][4], ql[4][4];

    const int krow = (lane & 7) + ((lane >> 3) & 1) * 8;
    const int kch  = (lane >> 4) * 16;

    for (int t = 0; t < 8; t++) {
        cp_wait<0>();
        __syncthreads();

        if (t == 0) {
            #pragma unroll
            for (int ks = 0; ks < 4; ks++) {
                uint32_t ad = SW128((w * 16 + (lane & 15)) * 128 + ks * 32 + (lane >> 4) * 16);
                ldsm4(qh[ks][0], qh[ks][1], qh[ks][2], qh[ks][3], sb + ad);
                ldsm4(ql[ks][0], ql[ks][1], ql[ks][2], ql[ks][3], sb + 16384 + ad);
            }
        }

        if (t < 7) { load_kv(t + 1, (t + 1) & 1); cp_commit(); }
        else       { cp_commit(); }

        uint32_t kb = sb + 32768 + (t & 1) * 32768;

        float sacc[8][4];
        #pragma unroll
        for (int ni = 0; ni < 8; ni++)
            #pragma unroll
            for (int j = 0; j < 4; j++) sacc[ni][j] = 0.f;

        #pragma unroll
        for (int ks = 0; ks < 4; ks++) {
            #pragma unroll
            for (int nj = 0; nj < 4; nj++) {
                uint32_t ad = SW128((nj * 16 + krow) * 128 + ks * 32 + kch);
                uint32_t h0, h1, h2, h3, e0, e1, e2, e3;
                ldsm4(h0, h1, h2, h3, kb + ad);
                ldsm4(e0, e1, e2, e3, kb + 8192 + ad);
                mma16816(sacc[2*nj][0], sacc[2*nj][1], sacc[2*nj][2], sacc[2*nj][3],
                         qh[ks][0], qh[ks][1], qh[ks][2], qh[ks][3], h0, h2);
                mma16816(sacc[2*nj+1][0], sacc[2*nj+1][1], sacc[2*nj+1][2], sacc[2*nj+1][3],
                         qh[ks][0], qh[ks][1], qh[ks][2], qh[ks][3], h1, h3);
                mma16816(sacc[2*nj][0], sacc[2*nj][1], sacc[2*nj][2], sacc[2*nj][3],
                         qh[ks][0], qh[ks][1], qh[ks][2], qh[ks][3], e0, e2);
                mma16816(sacc[2*nj+1][0], sacc[2*nj+1][1], sacc[2*nj+1][2], sacc[2*nj+1][3],
                         qh[ks][0], qh[ks][1], qh[ks][2], qh[ks][3], e1, e3);
                mma16816(sacc[2*nj][0], sacc[2*nj][1], sacc[2*nj][2], sacc[2*nj][3],
                         ql[ks][0], ql[ks][1], ql[ks][2], ql[ks][3], h0, h2);
                mma16816(sacc[2*nj+1][0], sacc[2*nj+1][1], sacc[2*nj+1][2], sacc[2*nj+1][3],
                         ql[ks][0], ql[ks][1], ql[ks][2], ql[ks][3], h1, h3);
            }
        }

        float ml0 = -1e30f, ml1 = -1e30f;
        #pragma unroll
        for (int ni = 0; ni < 8; ni++) {
            sacc[ni][0] *= 0.125f; sacc[ni][1] *= 0.125f;
            sacc[ni][2] *= 0.125f; sacc[ni][3] *= 0.125f;
            ml0 = fmaxf(ml0, fmaxf(sacc[ni][0], sacc[ni][1]));
            ml1 = fmaxf(ml1, fmaxf(sacc[ni][2], sacc[ni][3]));
        }
        ml0 = fmaxf(ml0, __shfl_xor_sync(0xffffffffu, ml0, 1));
        ml0 = fmaxf(ml0, __shfl_xor_sync(0xffffffffu, ml0, 2));
        ml1 = fmaxf(ml1, __shfl_xor_sync(0xffffffffu, ml1, 1));
        ml1 = fmaxf(ml1, __shfl_xor_sync(0xffffffffu, ml1, 2));

        float mn0 = fmaxf(m0, ml0), mn1 = fmaxf(m1, ml1);
        float corr0 = __expf(m0 - mn0), corr1 = __expf(m1 - mn1);
        m0 = mn0; m1 = mn1;

        float rs0 = 0.f, rs1 = 0.f;
        #pragma unroll
        for (int ni = 0; ni < 8; ni++) {
            sacc[ni][0] = __expf(sacc[ni][0] - mn0);
            sacc[ni][1] = __expf(sacc[ni][1] - mn0);
            sacc[ni][2] = __expf(sacc[ni][2] - mn1);
            sacc[ni][3] = __expf(sacc[ni][3] - mn1);
            rs0 += sacc[ni][0] + sacc[ni][1];
            rs1 += sacc[ni][2] + sacc[ni][3];
        }
        rs0 += __shfl_xor_sync(0xffffffffu, rs0, 1);
        rs0 += __shfl_xor_sync(0xffffffffu, rs0, 2);
        rs1 += __shfl_xor_sync(0xffffffffu, rs1, 1);
        rs1 += __shfl_xor_sync(0xffffffffu, rs1, 2);
        l0 = l0 * corr0 + rs0;
        l1 = l1 * corr1 + rs1;
        #pragma unroll
        for (int ni = 0; ni < 8; ni++) {
            oacc[ni][0] *= corr0; oacc[ni][1] *= corr0;
            oacc[ni][2] *= corr1; oacc[ni][3] *= corr1;
        }

        #pragma unroll
        for (int ks = 0; ks < 4; ks++) {
            float* p0 = sacc[2 * ks];
            float* p1 = sacc[2 * ks + 1];
            uint32_t ah0 = pack_hi(p0[0], p0[1]);
            uint32_t ah1 = pack_hi(p0[2], p0[3]);
            uint32_t ah2 = pack_hi(p1[0], p1[1]);
            uint32_t ah3 = pack_hi(p1[2], p1[3]);
            uint32_t al0 = pack_rn(p0[0] - trunc_bf(p0[0]), p0[1] - trunc_bf(p0[1]));
            uint32_t al1 = pack_rn(p0[2] - trunc_bf(p0[2]), p0[3] - trunc_bf(p0[3]));
            uint32_t al2 = pack_rn(p1[0] - trunc_bf(p1[0]), p1[1] - trunc_bf(p1[1]));
            uint32_t al3 = pack_rn(p1[2] - trunc_bf(p1[2]), p1[3] - trunc_bf(p1[3]));
            #pragma unroll
            for (int ep = 0; ep < 4; ep++) {
                uint32_t ad = SW128((ks * 16 + krow) * 128 + ep * 32 + kch);
                uint32_t vh0, vh1, vh2, vh3, vl0_, vl1_, vl2_, vl3_;
                ldsm4t(vh0, vh1, vh2, vh3, kb + 16384 + ad);
                ldsm4t(vl0_, vl1_, vl2_, vl3_, kb + 24576 + ad);
                mma16816(oacc[2*ep][0], oacc[2*ep][1], oacc[2*ep][2], oacc[2*ep][3],
                         ah0, ah1, ah2, ah3, vh0, vh1);
                mma16816(oacc[2*ep+1][0], oacc[2*ep+1][1], oacc[2*ep+1][2], oacc[2*ep+1][3],
                         ah0, ah1, ah2, ah3, vh2, vh3);
                mma16816(oacc[2*ep][0], oacc[2*ep][1], oacc[2*ep][2], oacc[2*ep][3],
                         ah0, ah1, ah2, ah3, vl0_, vl1_);
                mma16816(oacc[2*ep+1][0], oacc[2*ep+1][1], oacc[2*ep+1][2], oacc[2*ep+1][3],
                         ah0, ah1, ah2, ah3, vl2_, vl3_);
                mma16816(oacc[2*ep][0], oacc[2*ep][1], oacc[2*ep][2], oacc[2*ep][3],
                         al0, al1, al2, al3, vh0, vh1);
                mma16816(oacc[2*ep+1][0], oacc[2*ep+1][1], oacc[2*ep+1][2], oacc[2*ep+1][3],
                         al0, al1, al2, al3, vh2, vh3);
            }
        }
    }

    // epilogue (round-7 verbatim): normalize + write hi/lo rows
    float inv0 = 1.f / l0, inv1 = 1.f / l1;
    int mrow = b * SS + qt * 128 + w * 16 + (lane >> 2);
    int colb = h * 64 + (lane & 3) * 2;
    #pragma unroll
    for (int ni = 0; ni < 8; ni++) {
        float v0 = oacc[ni][0] * inv0, v1 = oacc[ni][1] * inv0;
        float v2 = oacc[ni][2] * inv1, v3 = oacc[ni][3] * inv1;
        size_t base0 = (size_t)mrow * DD + colb + ni * 8;
        size_t base1 = (size_t)(mrow + 8) * DD + colb + ni * 8;
        *(uint32_t*)(g_ashi + base0) = pack_hi(v0, v1);
        *(uint32_t*)(g_aslo + base0) = pack_rn(v0 - trunc_bf(v0), v1 - trunc_bf(v1));
        *(uint32_t*)(g_ashi + base1) = pack_hi(v2, v3);
        *(uint32_t*)(g_aslo + base1) = pack_rn(v2 - trunc_bf(v2), v3 - trunc_bf(v3));
    }
}

// ---------------------------------------------------------------------------
extern "C" void kernel_launch(void* const* d_in, const int* in_sizes, int n_in,
                              void* d_out, int out_size)
{
    const float* x  = (const float*)d_in[0];
    const float* Wq = (const float*)d_in[1];
    const float* Wk = (const float*)d_in[2];
    const float* Wv = (const float*)d_in[3];
    const float* bq = (const float*)d_in[4];
    const float* bk = (const float*)d_in[5];
    const float* bv = (const float*)d_in[6];
    const float* Wo = (const float*)d_in[7];
    const float* bo = (const float*)d_in[8];
    float* out = (float*)d_out;

    cudaFuncSetAttribute(gemm_kernel, cudaFuncAttributeMaxDynamicSharedMemorySize, G_SMEM);
    cudaFuncSetAttribute(attn_kernel, cudaFuncAttributeMaxDynamicSharedMemorySize, AT_SMEM);
    cudaFuncSetAttribute(gemm_proj_i8, cudaFuncAttributeMaxDynamicSharedMemorySize, I_SMEM);

    prep_x<<<(M_TOT * DD + 255) / 256, 256>>>(x);
    prep_wqkv<<<(N_QKV * DD + 255) / 256, 256>>>(Wq, Wk, Wv);
    quant_wo<<<DD, 256>>>(Wo);

    gemm_kernel<<<dim3(N_QKV / 128, M_TOT / 256), 256, G_SMEM>>>(bq, bk, bv);

    attn_kernel<<<dim3(SS / 128, HH, BB), 256, AT_SMEM>>>();

    quant_att<<<M_TOT, 256>>>();

    gemm_proj_i8<<<dim3(DD / 64, M_TOT / 128), 256, I_SMEM>>>(bo, out);
}